// round 2
// baseline (speedup 1.0000x reference)
#include <cuda_runtime.h>
#include <cstdint>

#define NB 16
#define NT 128
#define NN 256
#define NF 128

typedef unsigned long long ull;

__device__ __forceinline__ ull pack2(float lo, float hi) {
    ull r;
    asm("mov.b64 %0, {%1,%2};" : "=l"(r) : "f"(lo), "f"(hi));
    return r;
}
__device__ __forceinline__ void unpack2(ull v, float& lo, float& hi) {
    asm("mov.b64 {%0,%1}, %2;" : "=f"(lo), "=f"(hi) : "l"(v));
}
__device__ __forceinline__ ull fma2_(ull a, ull b, ull c) {
    ull d;
    asm("fma.rn.f32x2 %0, %1, %2, %3;" : "=l"(d) : "l"(a), "l"(b), "l"(c));
    return d;
}

__device__ __forceinline__ float warp_sum(float v) {
#pragma unroll
    for (int o = 16; o; o >>= 1) v += __shfl_xor_sync(0xffffffffu, v, o);
    return v;
}
__device__ __forceinline__ float warp_max(float v) {
#pragma unroll
    for (int o = 16; o; o >>= 1) v = fmaxf(v, __shfl_xor_sync(0xffffffffu, v, o));
    return v;
}

// Shared memory layout (floats):
//   Xs  [128][128]   x+te, later overwritten per-row with post-attn LN output U
//   Ks  [128][129]   K projection (padded stride for column reads in S-GEMM)
//   Vs  [128][128]   V projection
//   B1s [32][128]    Q -> AO -> H chunk buffer
//   B2s [32][128]    S/probs chunk buffer; ALIASES Wbuf (weight staging, 8x128)
#define OFF_K   (128 * 128)
#define OFF_V   (OFF_K + 128 * 129)
#define OFF_B1  (OFF_V + 128 * 128)
#define OFF_B2  (OFF_B1 + 32 * 128)
#define SMEM_FLOATS (OFF_B2 + 32 * 128)   // 57472 floats = 229888 bytes

// ---------------------------------------------------------------------------
// 128x128 GEMM: C[128][128] = A[128][128](smem) @ Wg[128][128](global) + bg
// 256 threads, 8x8 register tile per thread (as 8 rows x 4 f32x2 col-pairs).
// ---------------------------------------------------------------------------
__device__ void gemm128(const float* __restrict__ A, const float* __restrict__ Wg,
                        const float* __restrict__ bg, float* C, int sC,
                        float* Wbuf, int tid) {
    const int ty = tid >> 4;      // 0..15 -> rows 8*ty .. 8*ty+7
    const int tx = tid & 15;      // 0..15 -> col pairs {2*tx + 32*cc, +1}
    ull acc[8][4];
#pragma unroll
    for (int cc = 0; cc < 4; cc++) {
        ull bv = pack2(bg[2 * tx + 32 * cc], bg[2 * tx + 32 * cc + 1]);
#pragma unroll
        for (int rr = 0; rr < 8; rr++) acc[rr][cc] = bv;
    }
    for (int k0 = 0; k0 < 128; k0 += 8) {
        __syncthreads();   // protect Wbuf before overwrite
#pragma unroll
        for (int i = 0; i < 4; i++) {
            int e = tid + 256 * i;   // 1024 elements: Wbuf[8][128]
            Wbuf[e] = Wg[(k0 + (e >> 7)) * 128 + (e & 127)];
        }
        __syncthreads();
#pragma unroll
        for (int kk = 0; kk < 8; kk++) {
            ull a2[8];
#pragma unroll
            for (int rr = 0; rr < 8; rr++) {
                float a = A[(8 * ty + rr) * 128 + k0 + kk];
                a2[rr] = pack2(a, a);
            }
            ull w2[4];
#pragma unroll
            for (int cc = 0; cc < 4; cc++)
                w2[cc] = *(const ull*)(Wbuf + kk * 128 + 2 * tx + 32 * cc);
#pragma unroll
            for (int rr = 0; rr < 8; rr++)
#pragma unroll
                for (int cc = 0; cc < 4; cc++)
                    acc[rr][cc] = fma2_(a2[rr], w2[cc], acc[rr][cc]);
        }
    }
#pragma unroll
    for (int rr = 0; rr < 8; rr++)
#pragma unroll
        for (int cc = 0; cc < 4; cc++) {
            float lo, hi;
            unpack2(acc[rr][cc], lo, hi);
            int r = 8 * ty + rr, c = 2 * tx + 32 * cc;
            C[r * sC + c] = lo;
            C[r * sC + c + 1] = hi;
        }
}

// ---------------------------------------------------------------------------
// 32x128 GEMM core: acc = A[32 rows](smem, stride 128) @ Wg(global) + bg
// 256 threads: 4 rows x 2 f32x2 col-pairs per thread.
// ---------------------------------------------------------------------------
__device__ __forceinline__ void gemm32_core(const float* __restrict__ A,
                                            const float* __restrict__ Wg,
                                            const float* __restrict__ bg,
                                            float* Wbuf, int tid, ull acc[4][2]) {
    const int ty = tid >> 5;   // 0..7 -> rows 4*ty .. 4*ty+3
    const int tx = tid & 31;   // col pairs {2*tx + 64*cc, +1}
#pragma unroll
    for (int cc = 0; cc < 2; cc++) {
        ull bv = pack2(bg[2 * tx + 64 * cc], bg[2 * tx + 64 * cc + 1]);
#pragma unroll
        for (int rr = 0; rr < 4; rr++) acc[rr][cc] = bv;
    }
    for (int k0 = 0; k0 < 128; k0 += 8) {
        __syncthreads();
#pragma unroll
        for (int i = 0; i < 4; i++) {
            int e = tid + 256 * i;
            Wbuf[e] = Wg[(k0 + (e >> 7)) * 128 + (e & 127)];
        }
        __syncthreads();
#pragma unroll
        for (int kk = 0; kk < 8; kk++) {
            ull a2[4];
#pragma unroll
            for (int rr = 0; rr < 4; rr++) {
                float a = A[(4 * ty + rr) * 128 + k0 + kk];
                a2[rr] = pack2(a, a);
            }
            ull w2[2];
#pragma unroll
            for (int cc = 0; cc < 2; cc++)
                w2[cc] = *(const ull*)(Wbuf + kk * 128 + 2 * tx + 64 * cc);
#pragma unroll
            for (int rr = 0; rr < 4; rr++)
#pragma unroll
                for (int cc = 0; cc < 2; cc++)
                    acc[rr][cc] = fma2_(a2[rr], w2[cc], acc[rr][cc]);
        }
    }
}

__device__ void gemm32_store(const float* A, const float* Wg, const float* bg,
                             float* C, float* Wbuf, int tid, bool relu) {
    ull acc[4][2];
    gemm32_core(A, Wg, bg, Wbuf, tid, acc);
    const int ty = tid >> 5, tx = tid & 31;
#pragma unroll
    for (int rr = 0; rr < 4; rr++)
#pragma unroll
        for (int cc = 0; cc < 2; cc++) {
            float lo, hi;
            unpack2(acc[rr][cc], lo, hi);
            if (relu) { lo = fmaxf(lo, 0.0f); hi = fmaxf(hi, 0.0f); }
            int r = 4 * ty + rr, c = 2 * tx + 64 * cc;
            C[r * 128 + c] = lo;
            C[r * 128 + c + 1] = hi;
        }
}

// S[32][128] = 0.25 * Q[32][128] @ Ks[128][129]^T (scores; mask applied in softmax)
__device__ void gemmS(const float* __restrict__ Q, const float* __restrict__ Ks,
                      float* S, int tid) {
    const int ty = tid >> 5, tx = tid & 31;
    ull acc[4][2];
#pragma unroll
    for (int rr = 0; rr < 4; rr++)
#pragma unroll
        for (int cc = 0; cc < 2; cc++) acc[rr][cc] = 0ull;
#pragma unroll 4
    for (int k = 0; k < 128; k++) {
        ull a2[4];
#pragma unroll
        for (int rr = 0; rr < 4; rr++) {
            float a = Q[(4 * ty + rr) * 128 + k];
            a2[rr] = pack2(a, a);
        }
        ull w2[2];
#pragma unroll
        for (int cc = 0; cc < 2; cc++) {
            int j = 2 * tx + 64 * cc;
            w2[cc] = pack2(Ks[j * 129 + k], Ks[(j + 1) * 129 + k]);
        }
#pragma unroll
        for (int rr = 0; rr < 4; rr++)
#pragma unroll
            for (int cc = 0; cc < 2; cc++)
                acc[rr][cc] = fma2_(a2[rr], w2[cc], acc[rr][cc]);
    }
#pragma unroll
    for (int rr = 0; rr < 4; rr++)
#pragma unroll
        for (int cc = 0; cc < 2; cc++) {
            float lo, hi;
            unpack2(acc[rr][cc], lo, hi);
            int r = 4 * ty + rr, j = 2 * tx + 64 * cc;
            S[r * 128 + j] = lo * 0.25f;
            S[r * 128 + j + 1] = hi * 0.25f;
        }
}

// AO[32][128] = P[32][128] @ Vs[128][128]
__device__ void gemmAV(const float* __restrict__ P, const float* __restrict__ Vs,
                       float* AO, int tid) {
    const int ty = tid >> 5, tx = tid & 31;
    ull acc[4][2];
#pragma unroll
    for (int rr = 0; rr < 4; rr++)
#pragma unroll
        for (int cc = 0; cc < 2; cc++) acc[rr][cc] = 0ull;
#pragma unroll 4
    for (int k = 0; k < 128; k++) {
        ull a2[4];
#pragma unroll
        for (int rr = 0; rr < 4; rr++) {
            float a = P[(4 * ty + rr) * 128 + k];
            a2[rr] = pack2(a, a);
        }
        ull w2[2];
#pragma unroll
        for (int cc = 0; cc < 2; cc++)
            w2[cc] = *(const ull*)(Vs + k * 128 + 2 * tx + 64 * cc);
#pragma unroll
        for (int rr = 0; rr < 4; rr++)
#pragma unroll
            for (int cc = 0; cc < 2; cc++)
                acc[rr][cc] = fma2_(a2[rr], w2[cc], acc[rr][cc]);
    }
#pragma unroll
    for (int rr = 0; rr < 4; rr++)
#pragma unroll
        for (int cc = 0; cc < 2; cc++) {
            float lo, hi;
            unpack2(acc[rr][cc], lo, hi);
            int r = 4 * ty + rr, c = 2 * tx + 64 * cc;
            AO[r * 128 + c] = lo;
            AO[r * 128 + c + 1] = hi;
        }
}

// Causal softmax on S[32][128]; masked entries (j > t) become exactly 0
// (matches reference: exp(-32767 - max) underflows to 0 in fp32).
__device__ void softmax32(float* S, int c0, int tid) {
    const int w = tid >> 5, lane = tid & 31;
#pragma unroll
    for (int i = 0; i < 4; i++) {
        int lr = 4 * w + i;
        int t = c0 + lr;
        float e[4];
        float mx = -3.0e38f;
#pragma unroll
        for (int q = 0; q < 4; q++) {
            int j = lane + 32 * q;
            float v = (j <= t) ? S[lr * 128 + j] : -3.0e38f;
            e[q] = v;
            mx = fmaxf(mx, v);
        }
        mx = warp_max(mx);
        float sum = 0.0f;
#pragma unroll
        for (int q = 0; q < 4; q++) {
            int j = lane + 32 * q;
            float p = (j <= t) ? __expf(e[q] - mx) : 0.0f;
            e[q] = p;
            sum += p;
        }
        sum = warp_sum(sum);
        float inv = 1.0f / sum;
#pragma unroll
        for (int q = 0; q < 4; q++) {
            int j = lane + 32 * q;
            S[lr * 128 + j] = e[q] * inv;
        }
    }
}

// O-proj + residual(+X) + LayerNorm, result U written back into Xs rows.
__device__ void oproj_ln(const float* AO, const float* __restrict__ Wg,
                         const float* __restrict__ bg, float* Xs, int c0,
                         float* Wbuf, int tid) {
    ull acc[4][2];
    gemm32_core(AO, Wg, bg, Wbuf, tid, acc);
    const int ty = tid >> 5, tx = tid & 31;
#pragma unroll
    for (int rr = 0; rr < 4; rr++) {
        int r = c0 + 4 * ty + rr;
        float2 x0 = *(const float2*)(Xs + r * 128 + 2 * tx);
        float2 x1 = *(const float2*)(Xs + r * 128 + 2 * tx + 64);
        float a0, b0, a1, b1;
        unpack2(acc[rr][0], a0, b0);
        unpack2(acc[rr][1], a1, b1);
        a0 += x0.x; b0 += x0.y; a1 += x1.x; b1 += x1.y;
        float s = warp_sum(a0 + b0 + a1 + b1);
        float mu = s * (1.0f / 128.0f);
        a0 -= mu; b0 -= mu; a1 -= mu; b1 -= mu;
        float q = warp_sum(a0 * a0 + b0 * b0 + a1 * a1 + b1 * b1);
        float inv = rsqrtf(q * (1.0f / 128.0f) + 1e-5f);
        *(float2*)(Xs + r * 128 + 2 * tx) = make_float2(a0 * inv, b0 * inv);
        *(float2*)(Xs + r * 128 + 2 * tx + 64) = make_float2(a1 * inv, b1 * inv);
    }
}

// FFN2 + residual(+U from Xs) + LayerNorm, written straight to global out.
__device__ void ffn2_ln(const float* H, const float* __restrict__ Wg,
                        const float* __restrict__ bg, const float* Xs, int c0,
                        float* __restrict__ outbn, float* Wbuf, int tid) {
    ull acc[4][2];
    gemm32_core(H, Wg, bg, Wbuf, tid, acc);
    const int ty = tid >> 5, tx = tid & 31;
#pragma unroll
    for (int rr = 0; rr < 4; rr++) {
        int r = c0 + 4 * ty + rr;
        float2 u0 = *(const float2*)(Xs + r * 128 + 2 * tx);
        float2 u1 = *(const float2*)(Xs + r * 128 + 2 * tx + 64);
        float a0, b0, a1, b1;
        unpack2(acc[rr][0], a0, b0);
        unpack2(acc[rr][1], a1, b1);
        a0 += u0.x; b0 += u0.y; a1 += u1.x; b1 += u1.y;
        float s = warp_sum(a0 + b0 + a1 + b1);
        float mu = s * (1.0f / 128.0f);
        a0 -= mu; b0 -= mu; a1 -= mu; b1 -= mu;
        float q = warp_sum(a0 * a0 + b0 * b0 + a1 * a1 + b1 * b1);
        float inv = rsqrtf(q * (1.0f / 128.0f) + 1e-5f);
        float* orow = outbn + (size_t)r * (NN * NF);
        *(float2*)(orow + 2 * tx) = make_float2(a0 * inv, b0 * inv);
        *(float2*)(orow + 2 * tx + 64) = make_float2(a1 * inv, b1 * inv);
    }
}

__global__ void __launch_bounds__(256, 1)
fused_tattn(const float* __restrict__ x, const float* __restrict__ te,
            const float* __restrict__ wq, const float* __restrict__ bq,
            const float* __restrict__ wk, const float* __restrict__ bk,
            const float* __restrict__ wv, const float* __restrict__ bv,
            const float* __restrict__ wo, const float* __restrict__ bo,
            const float* __restrict__ w1, const float* __restrict__ b1,
            const float* __restrict__ w2, const float* __restrict__ b2,
            float* __restrict__ out) {
    extern __shared__ float sm[];
    float* Xs = sm;
    float* Ks = sm + OFF_K;
    float* Vs = sm + OFF_V;
    float* B1s = sm + OFF_B1;
    float* B2s = sm + OFF_B2;
    float* Wbuf = B2s;   // alias: weight staging never live at same time as S

    const int tid = threadIdx.x;
    const int bn = blockIdx.x;
    const int b = bn >> 8;       // / 256
    const int n = bn & 255;      // % 256

    const size_t tstride = (size_t)NN * NF;  // stride between consecutive t
    const float* xb = x + (size_t)b * NT * tstride + (size_t)n * NF;
    const float* tb = te + (size_t)b * NT * tstride + (size_t)n * NF;

    // Load X = x + te  (128 rows x 32 float4)
#pragma unroll
    for (int i = 0; i < 16; i++) {
        int e = tid + 256 * i;          // 4096 float4s
        int t = e >> 5, f4 = e & 31;
        float4 a = *(const float4*)(xb + (size_t)t * tstride + f4 * 4);
        float4 c = *(const float4*)(tb + (size_t)t * tstride + f4 * 4);
        a.x += c.x; a.y += c.y; a.z += c.z; a.w += c.w;
        *(float4*)(Xs + t * 128 + f4 * 4) = a;
    }
    __syncthreads();

    // K and V projections over the full 128 tokens
    gemm128(Xs, wk, bk, Ks, 129, Wbuf, tid);
    gemm128(Xs, wv, bv, Vs, 128, Wbuf, tid);

    float* outbn = out + (size_t)b * NT * tstride + (size_t)n * NF;

    // Process queries in 4 chunks of 32 rows; everything after attention is
    // row-local so each chunk completes through the final LN.
    for (int c = 0; c < 4; c++) {
        int c0 = 32 * c;
        gemm32_store(Xs + c0 * 128, wq, bq, B1s, Wbuf, tid, false);   // Q
        __syncthreads();
        gemmS(B1s, Ks, B2s, tid);                                     // scores
        __syncthreads();
        softmax32(B2s, c0, tid);                                      // probs
        __syncthreads();
        gemmAV(B2s, Vs, B1s, tid);                                    // attn out
        __syncthreads();
        oproj_ln(B1s, wo, bo, Xs, c0, Wbuf, tid);                     // U -> Xs
        __syncthreads();
        gemm32_store(Xs + c0 * 128, w1, b1, B1s, Wbuf, tid, true);    // H=relu
        __syncthreads();
        ffn2_ln(B1s, w2, b2, Xs, c0, outbn, Wbuf, tid);               // -> out
        __syncthreads();
    }
}

extern "C" void kernel_launch(void* const* d_in, const int* in_sizes, int n_in,
                              void* d_out, int out_size) {
    const float* x  = (const float*)d_in[0];
    const float* te = (const float*)d_in[1];
    const float* wq = (const float*)d_in[2];
    const float* bq = (const float*)d_in[3];
    const float* wk = (const float*)d_in[4];
    const float* bk = (const float*)d_in[5];
    const float* wv = (const float*)d_in[6];
    const float* bv = (const float*)d_in[7];
    const float* wo = (const float*)d_in[8];
    const float* bo = (const float*)d_in[9];
    const float* w1 = (const float*)d_in[10];
    const float* b1 = (const float*)d_in[11];
    const float* w2 = (const float*)d_in[12];
    const float* b2 = (const float*)d_in[13];
    float* out = (float*)d_out;

    const int smem = SMEM_FLOATS * (int)sizeof(float);  // 229888 bytes
    cudaFuncSetAttribute(fused_tattn, cudaFuncAttributeMaxDynamicSharedMemorySize, smem);
    fused_tattn<<<NB * NN, 256, smem>>>(x, te, wq, bq, wk, bk, wv, bv,
                                        wo, bo, w1, b1, w2, b2, out);
}

// round 3
// speedup vs baseline: 1.4623x; 1.4623x over previous
#include <cuda_runtime.h>
#include <cstdint>

#define NB 16
#define NT 128
#define NN 256
#define NF 128

typedef unsigned long long ull;

__device__ __forceinline__ ull pack2(float lo, float hi) {
    ull r;
    asm("mov.b64 %0, {%1,%2};" : "=l"(r) : "f"(lo), "f"(hi));
    return r;
}
__device__ __forceinline__ void unpack2(ull v, float& lo, float& hi) {
    asm("mov.b64 {%0,%1}, %2;" : "=f"(lo), "=f"(hi) : "l"(v));
}
__device__ __forceinline__ ull fma2_(ull a, ull b, ull c) {
    ull d;
    asm("fma.rn.f32x2 %0, %1, %2, %3;" : "=l"(d) : "l"(a), "l"(b), "l"(c));
    return d;
}

__device__ __forceinline__ float warp_sum(float v) {
#pragma unroll
    for (int o = 16; o; o >>= 1) v += __shfl_xor_sync(0xffffffffu, v, o);
    return v;
}
__device__ __forceinline__ float warp_max(float v) {
#pragma unroll
    for (int o = 16; o; o >>= 1) v = fmaxf(v, __shfl_xor_sync(0xffffffffu, v, o));
    return v;
}

// Shared memory layout (floats):
//   Xs  [128][128]  x+te, later rows replaced by post-attn LN output U
//   KsT [128][128]  K^T : KsT[k][j] = K[j][k]  (so S-GEMM reads it like V)
//   Vs  [128][128]
//   B1s [32][128]   Q / AO / H chunk buffer; also W-stage double buffer (KV phase)
//   B2s [32][128]   S / probs buffer; W-stage buffer everywhere
#define OFF_KT  (128 * 128)
#define OFF_V   (OFF_KT + 128 * 128)
#define OFF_B1  (OFF_V + 128 * 128)
#define OFF_B2  (OFF_B1 + 32 * 128)
#define SMEM_FLOATS (OFF_B2 + 32 * 128)   // 57344 floats = 229376 bytes

// ---- weight-stage copy helpers: 32 k-rows (4096 floats) per stage ----------
__device__ __forceinline__ void wload(const float* __restrict__ Wg, int k0,
                                      int tid, float4 p[4]) {
    const float4* s = reinterpret_cast<const float4*>(Wg) + k0 * 32;
#pragma unroll
    for (int i = 0; i < 4; i++) p[i] = s[tid + 256 * i];
}
__device__ __forceinline__ void wstore(float* Wbuf, int tid, const float4 p[4]) {
    float4* d = reinterpret_cast<float4*>(Wbuf);
#pragma unroll
    for (int i = 0; i < 4; i++) d[tid + 256 * i] = p[i];
}

// ---------------------------------------------------------------------------
// 128x128x128 GEMM: C = A(smem) @ Wg(global) + bg
// 256 threads, 8 rows x 8 cols per thread. Double-buffered 32-k weight
// stages through buf0/buf1 with register prefetch (1 barrier per stage).
// MODE 0: C row-major stride 128.  MODE 1: store transposed (C[j][r]).
// ---------------------------------------------------------------------------
template <int MODE>
__device__ void gemm128(const float* __restrict__ A, const float* __restrict__ Wg,
                        const float* __restrict__ bg, float* C,
                        float* buf0, float* buf1, int tid) {
    const int ty = tid >> 4, tx = tid & 15;
    const int r0 = 8 * ty, c0 = 8 * tx;
    ull acc[8][4];
    {
        float4 bA = *(const float4*)(bg + c0);
        float4 bB = *(const float4*)(bg + c0 + 4);
        ull b0 = pack2(bA.x, bA.y), b1 = pack2(bA.z, bA.w);
        ull b2 = pack2(bB.x, bB.y), b3 = pack2(bB.z, bB.w);
#pragma unroll
        for (int rr = 0; rr < 8; rr++) {
            acc[rr][0] = b0; acc[rr][1] = b1; acc[rr][2] = b2; acc[rr][3] = b3;
        }
    }
    {
        float4 p[4];
        wload(Wg, 0, tid, p);
        wstore(buf0, tid, p);
    }
    __syncthreads();
    for (int s = 0; s < 4; s++) {
        float4 p[4];
        if (s < 3) wload(Wg, 32 * (s + 1), tid, p);
        const float* Wb = (s & 1) ? buf1 : buf0;
        const int kb = 32 * s;
#pragma unroll 2
        for (int g = 0; g < 8; g++) {
            float4 a4[8];
#pragma unroll
            for (int rr = 0; rr < 8; rr++)
                a4[rr] = *(const float4*)(A + (r0 + rr) * 128 + kb + 4 * g);
            const float* wrow = Wb + (4 * g) * 128 + c0;
#pragma unroll
            for (int kkk = 0; kkk < 4; kkk++) {
                float4 w0 = *(const float4*)(wrow + kkk * 128);
                float4 w1 = *(const float4*)(wrow + kkk * 128 + 4);
                ull wA = pack2(w0.x, w0.y), wB = pack2(w0.z, w0.w);
                ull wC = pack2(w1.x, w1.y), wD = pack2(w1.z, w1.w);
#pragma unroll
                for (int rr = 0; rr < 8; rr++) {
                    float av = (kkk == 0) ? a4[rr].x : (kkk == 1) ? a4[rr].y
                             : (kkk == 2) ? a4[rr].z : a4[rr].w;
                    ull a2 = pack2(av, av);
                    acc[rr][0] = fma2_(a2, wA, acc[rr][0]);
                    acc[rr][1] = fma2_(a2, wB, acc[rr][1]);
                    acc[rr][2] = fma2_(a2, wC, acc[rr][2]);
                    acc[rr][3] = fma2_(a2, wD, acc[rr][3]);
                }
            }
        }
        if (s < 3) wstore((s & 1) ? buf0 : buf1, tid, p);
        __syncthreads();
    }
    if (MODE == 0) {
#pragma unroll
        for (int rr = 0; rr < 8; rr++) {
            float l0, h0, l1, h1, l2, h2, l3, h3;
            unpack2(acc[rr][0], l0, h0); unpack2(acc[rr][1], l1, h1);
            unpack2(acc[rr][2], l2, h2); unpack2(acc[rr][3], l3, h3);
            *(float4*)(C + (r0 + rr) * 128 + c0)     = make_float4(l0, h0, l1, h1);
            *(float4*)(C + (r0 + rr) * 128 + c0 + 4) = make_float4(l2, h2, l3, h3);
        }
    } else {
#pragma unroll
        for (int cc = 0; cc < 4; cc++) {
            float lo[8], hi[8];
#pragma unroll
            for (int rr = 0; rr < 8; rr++) unpack2(acc[rr][cc], lo[rr], hi[rr]);
            int j = c0 + 2 * cc;
            *(float4*)(C + j * 128 + r0)     = make_float4(lo[0], lo[1], lo[2], lo[3]);
            *(float4*)(C + j * 128 + r0 + 4) = make_float4(lo[4], lo[5], lo[6], lo[7]);
            *(float4*)(C + (j + 1) * 128 + r0)     = make_float4(hi[0], hi[1], hi[2], hi[3]);
            *(float4*)(C + (j + 1) * 128 + r0 + 4) = make_float4(hi[4], hi[5], hi[6], hi[7]);
        }
    }
}

// ---------------------------------------------------------------------------
// 32x128x128 GEMM core: acc = A(32 rows, stride 128) @ Wg + bg
// 256 threads: 4 rows x 4 cols per thread. Single-buffer 32-k stages in Wbuf
// with register prefetch (LDG for next stage hidden under current compute).
// Caller must __syncthreads() before entry (Wbuf gets overwritten at top).
// ---------------------------------------------------------------------------
__device__ __forceinline__ void gemm32_core(const float* __restrict__ A,
                                            const float* __restrict__ Wg,
                                            const float* __restrict__ bg,
                                            float* Wbuf, int tid, ull acc[4][2]) {
    const int ty = tid >> 5, tx = tid & 31;
    const int r0 = 4 * ty, c0 = 4 * tx;
    {
        float4 b4 = *(const float4*)(bg + c0);
        ull b0 = pack2(b4.x, b4.y), b1 = pack2(b4.z, b4.w);
#pragma unroll
        for (int rr = 0; rr < 4; rr++) { acc[rr][0] = b0; acc[rr][1] = b1; }
    }
    {
        float4 p[4];
        wload(Wg, 0, tid, p);
        wstore(Wbuf, tid, p);
    }
    __syncthreads();
    for (int s = 0; s < 4; s++) {
        float4 p[4];
        if (s < 3) wload(Wg, 32 * (s + 1), tid, p);
        const int kb = 32 * s;
#pragma unroll 4
        for (int g = 0; g < 8; g++) {
            float4 a4[4];
#pragma unroll
            for (int rr = 0; rr < 4; rr++)
                a4[rr] = *(const float4*)(A + (r0 + rr) * 128 + kb + 4 * g);
#pragma unroll
            for (int kkk = 0; kkk < 4; kkk++) {
                float4 w4 = *(const float4*)(Wbuf + (4 * g + kkk) * 128 + c0);
                ull wA = pack2(w4.x, w4.y), wB = pack2(w4.z, w4.w);
#pragma unroll
                for (int rr = 0; rr < 4; rr++) {
                    float av = (kkk == 0) ? a4[rr].x : (kkk == 1) ? a4[rr].y
                             : (kkk == 2) ? a4[rr].z : a4[rr].w;
                    ull a2 = pack2(av, av);
                    acc[rr][0] = fma2_(a2, wA, acc[rr][0]);
                    acc[rr][1] = fma2_(a2, wB, acc[rr][1]);
                }
            }
        }
        __syncthreads();                       // readers of Wbuf done
        if (s < 3) { wstore(Wbuf, tid, p); __syncthreads(); }
    }
}

// acc = A(32 rows) @ Bm(smem [128][128]); no bias, no staging.
__device__ __forceinline__ void gemm_sv_core(const float* __restrict__ A,
                                             const float* __restrict__ Bm,
                                             int tid, ull acc[4][2]) {
    const int ty = tid >> 5, tx = tid & 31;
    const int r0 = 4 * ty, c0 = 4 * tx;
#pragma unroll
    for (int rr = 0; rr < 4; rr++) { acc[rr][0] = 0ull; acc[rr][1] = 0ull; }
#pragma unroll 4
    for (int g = 0; g < 32; g++) {
        float4 a4[4];
#pragma unroll
        for (int rr = 0; rr < 4; rr++)
            a4[rr] = *(const float4*)(A + (r0 + rr) * 128 + 4 * g);
#pragma unroll
        for (int kkk = 0; kkk < 4; kkk++) {
            float4 w4 = *(const float4*)(Bm + (4 * g + kkk) * 128 + c0);
            ull wA = pack2(w4.x, w4.y), wB = pack2(w4.z, w4.w);
#pragma unroll
            for (int rr = 0; rr < 4; rr++) {
                float av = (kkk == 0) ? a4[rr].x : (kkk == 1) ? a4[rr].y
                         : (kkk == 2) ? a4[rr].z : a4[rr].w;
                ull a2 = pack2(av, av);
                acc[rr][0] = fma2_(a2, wA, acc[rr][0]);
                acc[rr][1] = fma2_(a2, wB, acc[rr][1]);
            }
        }
    }
}

__device__ __forceinline__ void store_acc32(ull acc[4][2], float* C, int tid,
                                            float scale, bool relu) {
    const int ty = tid >> 5, tx = tid & 31;
    const int r0 = 4 * ty, c0 = 4 * tx;
#pragma unroll
    for (int rr = 0; rr < 4; rr++) {
        float l0, h0, l1, h1;
        unpack2(acc[rr][0], l0, h0);
        unpack2(acc[rr][1], l1, h1);
        l0 *= scale; h0 *= scale; l1 *= scale; h1 *= scale;
        if (relu) {
            l0 = fmaxf(l0, 0.0f); h0 = fmaxf(h0, 0.0f);
            l1 = fmaxf(l1, 0.0f); h1 = fmaxf(h1, 0.0f);
        }
        *(float4*)(C + (r0 + rr) * 128 + c0) = make_float4(l0, h0, l1, h1);
    }
}

// Causal softmax on S[32][128] (rows are tokens c0chunk + lr).
__device__ void softmax32(float* S, int c0, int tid) {
    const int w = tid >> 5, lane = tid & 31;
#pragma unroll
    for (int i = 0; i < 4; i++) {
        int lr = 4 * w + i;
        int t = c0 + lr;
        float e[4];
        float mx = -3.0e38f;
#pragma unroll
        for (int q = 0; q < 4; q++) {
            int j = lane + 32 * q;
            float v = (j <= t) ? S[lr * 128 + j] : -3.0e38f;
            e[q] = v;
            mx = fmaxf(mx, v);
        }
        mx = warp_max(mx);
        float sum = 0.0f;
#pragma unroll
        for (int q = 0; q < 4; q++) {
            int j = lane + 32 * q;
            float p = (j <= t) ? __expf(e[q] - mx) : 0.0f;
            e[q] = p;
            sum += p;
        }
        sum = warp_sum(sum);
        float inv = 1.0f / sum;
#pragma unroll
        for (int q = 0; q < 4; q++) {
            int j = lane + 32 * q;
            S[lr * 128 + j] = e[q] * inv;
        }
    }
}

// acc + residual(base row from R) -> LayerNorm -> store (either smem or gmem).
__device__ __forceinline__ void ln_epilogue(ull acc[4][2], const float* R,
                                            float* dst, size_t dstride, int c0,
                                            int tid) {
    const int ty = tid >> 5, tx = tid & 31;
#pragma unroll
    for (int rr = 0; rr < 4; rr++) {
        int r = c0 + 4 * ty + rr;
        float4 x4 = *(const float4*)(R + r * 128 + 4 * tx);
        float e0, e1, e2, e3;
        unpack2(acc[rr][0], e0, e1);
        unpack2(acc[rr][1], e2, e3);
        e0 += x4.x; e1 += x4.y; e2 += x4.z; e3 += x4.w;
        float s = warp_sum(e0 + e1 + e2 + e3);
        float mu = s * (1.0f / 128.0f);
        e0 -= mu; e1 -= mu; e2 -= mu; e3 -= mu;
        float q = warp_sum(e0 * e0 + e1 * e1 + e2 * e2 + e3 * e3);
        float inv = rsqrtf(q * (1.0f / 128.0f) + 1e-5f);
        *(float4*)(dst + (size_t)r * dstride + 4 * tx) =
            make_float4(e0 * inv, e1 * inv, e2 * inv, e3 * inv);
    }
}

__global__ void __launch_bounds__(256, 1)
fused_tattn(const float* __restrict__ x, const float* __restrict__ te,
            const float* __restrict__ wq, const float* __restrict__ bq,
            const float* __restrict__ wk, const float* __restrict__ bk,
            const float* __restrict__ wv, const float* __restrict__ bv,
            const float* __restrict__ wo, const float* __restrict__ bo,
            const float* __restrict__ w1, const float* __restrict__ b1,
            const float* __restrict__ w2, const float* __restrict__ b2,
            float* __restrict__ out) {
    extern __shared__ float sm[];
    float* Xs  = sm;
    float* KsT = sm + OFF_KT;
    float* Vs  = sm + OFF_V;
    float* B1s = sm + OFF_B1;
    float* B2s = sm + OFF_B2;

    const int tid = threadIdx.x;
    const int bn = blockIdx.x;
    const int b = bn >> 8;
    const int n = bn & 255;

    const size_t tstride = (size_t)NN * NF;
    const float* xb = x + (size_t)b * NT * tstride + (size_t)n * NF;
    const float* tb = te + (size_t)b * NT * tstride + (size_t)n * NF;

    // X = x + te
#pragma unroll
    for (int i = 0; i < 16; i++) {
        int e = tid + 256 * i;          // 4096 float4s
        int t = e >> 5, f4 = e & 31;
        float4 a = *(const float4*)(xb + (size_t)t * tstride + f4 * 4);
        float4 c = *(const float4*)(tb + (size_t)t * tstride + f4 * 4);
        a.x += c.x; a.y += c.y; a.z += c.z; a.w += c.w;
        *(float4*)(Xs + t * 128 + f4 * 4) = a;
    }
    __syncthreads();

    // K (transposed into KsT) and V projections, double-buffered via B1/B2
    gemm128<1>(Xs, wk, bk, KsT, B1s, B2s, tid);
    gemm128<0>(Xs, wv, bv, Vs, B1s, B2s, tid);

    float* outbn = out + (size_t)b * NT * tstride + (size_t)n * NF;

    for (int c = 0; c < 4; c++) {
        const int c0 = 32 * c;
        const float* Ac = Xs + c0 * 128;

        {   // Q projection -> B1
            ull acc[4][2];
            gemm32_core(Ac, wq, bq, B2s, tid, acc);
            store_acc32(acc, B1s, tid, 1.0f, false);
        }
        __syncthreads();
        {   // scores S = 0.25 * Q @ K^T  -> B2
            ull acc[4][2];
            gemm_sv_core(B1s, KsT, tid, acc);
            store_acc32(acc, B2s, tid, 0.25f, false);
        }
        __syncthreads();
        softmax32(B2s, c0, tid);
        __syncthreads();
        {   // AO = P @ V -> B1
            ull acc[4][2];
            gemm_sv_core(B2s, Vs, tid, acc);
            store_acc32(acc, B1s, tid, 1.0f, false);
        }
        __syncthreads();
        {   // O-proj + residual + LN -> Xs rows
            ull acc[4][2];
            gemm32_core(B1s, wo, bo, B2s, tid, acc);
            ln_epilogue(acc, Xs, Xs, 128, c0, tid);
        }
        __syncthreads();
        {   // FFN1 (relu) -> B1
            ull acc[4][2];
            gemm32_core(Ac, w1, b1, B2s, tid, acc);
            store_acc32(acc, B1s, tid, 1.0f, true);
        }
        __syncthreads();
        {   // FFN2 + residual + LN -> global out
            ull acc[4][2];
            gemm32_core(B1s, w2, b2, B2s, tid, acc);
            ln_epilogue(acc, Xs, outbn, tstride, c0, tid);
        }
        __syncthreads();
    }
}

extern "C" void kernel_launch(void* const* d_in, const int* in_sizes, int n_in,
                              void* d_out, int out_size) {
    const float* x  = (const float*)d_in[0];
    const float* te = (const float*)d_in[1];
    const float* wq = (const float*)d_in[2];
    const float* bq = (const float*)d_in[3];
    const float* wk = (const float*)d_in[4];
    const float* bk = (const float*)d_in[5];
    const float* wv = (const float*)d_in[6];
    const float* bv = (const float*)d_in[7];
    const float* wo = (const float*)d_in[8];
    const float* bo = (const float*)d_in[9];
    const float* w1 = (const float*)d_in[10];
    const float* b1 = (const float*)d_in[11];
    const float* w2 = (const float*)d_in[12];
    const float* b2 = (const float*)d_in[13];
    float* out = (float*)d_out;

    const int smem = SMEM_FLOATS * (int)sizeof(float);  // 229376 bytes
    cudaFuncSetAttribute(fused_tattn, cudaFuncAttributeMaxDynamicSharedMemorySize, smem);
    fused_tattn<<<NB * NN, 256, smem>>>(x, te, wq, bq, wk, bk, wv, bv,
                                        wo, bo, w1, b1, w2, b2, out);
}

// round 4
// speedup vs baseline: 1.4624x; 1.0001x over previous
#include <cuda_runtime.h>
#include <cstdint>

#define NB 16
#define NT 128
#define NN 256
#define NF 128

typedef unsigned long long ull;

__device__ __forceinline__ ull pack2(float lo, float hi) {
    ull r;
    asm("mov.b64 %0, {%1,%2};" : "=l"(r) : "f"(lo), "f"(hi));
    return r;
}
__device__ __forceinline__ void unpack2(ull v, float& lo, float& hi) {
    asm("mov.b64 {%0,%1}, %2;" : "=f"(lo), "=f"(hi) : "l"(v));
}
__device__ __forceinline__ ull fma2_(ull a, ull b, ull c) {
    ull d;
    asm("fma.rn.f32x2 %0, %1, %2, %3;" : "=l"(d) : "l"(a), "l"(b), "l"(c));
    return d;
}

__device__ __forceinline__ float warp_sum(float v) {
#pragma unroll
    for (int o = 16; o; o >>= 1) v += __shfl_xor_sync(0xffffffffu, v, o);
    return v;
}
__device__ __forceinline__ float warp_max(float v) {
#pragma unroll
    for (int o = 16; o; o >>= 1) v = fmaxf(v, __shfl_xor_sync(0xffffffffu, v, o));
    return v;
}

// Shared memory layout (floats):
//   Xs  [128][128]  x+te, later rows replaced by post-attn LN output U
//   KsT [128][128]  K^T : KsT[k][j] = K[j][k]  (so S-GEMM reads it like V)
//   Vs  [128][128]
//   B1s [32][128]   Q / AO / H chunk buffer; also W-stage double buffer (KV phase)
//   B2s [32][128]   S / probs buffer; W-stage buffer everywhere
#define OFF_KT  (128 * 128)
#define OFF_V   (OFF_KT + 128 * 128)
#define OFF_B1  (OFF_V + 128 * 128)
#define OFF_B2  (OFF_B1 + 32 * 128)
#define SMEM_FLOATS (OFF_B2 + 32 * 128)   // 57344 floats = 229376 bytes

// ---- weight-stage copy helpers: 32 k-rows (4096 floats) per stage ----------
__device__ __forceinline__ void wload(const float* __restrict__ Wg, int k0,
                                      int tid, float4 p[4]) {
    const float4* s = reinterpret_cast<const float4*>(Wg) + k0 * 32;
#pragma unroll
    for (int i = 0; i < 4; i++) p[i] = s[tid + 256 * i];
}
__device__ __forceinline__ void wstore(float* Wbuf, int tid, const float4 p[4]) {
    float4* d = reinterpret_cast<float4*>(Wbuf);
#pragma unroll
    for (int i = 0; i < 4; i++) d[tid + 256 * i] = p[i];
}

// ---------------------------------------------------------------------------
// 128x128x128 GEMM: C = A(smem) @ Wg(global) + bg
// 256 threads, 8 rows x 8 cols per thread. Double-buffered 32-k weight
// stages through buf0/buf1 with register prefetch (1 barrier per stage).
// MODE 0: C row-major stride 128.  MODE 1: store transposed (C[j][r]).
// ---------------------------------------------------------------------------
template <int MODE>
__device__ void gemm128(const float* __restrict__ A, const float* __restrict__ Wg,
                        const float* __restrict__ bg, float* C,
                        float* buf0, float* buf1, int tid) {
    const int ty = tid >> 4, tx = tid & 15;
    const int r0 = 8 * ty, c0 = 8 * tx;
    ull acc[8][4];
    {
        float4 bA = *(const float4*)(bg + c0);
        float4 bB = *(const float4*)(bg + c0 + 4);
        ull b0 = pack2(bA.x, bA.y), b1 = pack2(bA.z, bA.w);
        ull b2 = pack2(bB.x, bB.y), b3 = pack2(bB.z, bB.w);
#pragma unroll
        for (int rr = 0; rr < 8; rr++) {
            acc[rr][0] = b0; acc[rr][1] = b1; acc[rr][2] = b2; acc[rr][3] = b3;
        }
    }
    {
        float4 p[4];
        wload(Wg, 0, tid, p);
        wstore(buf0, tid, p);
    }
    __syncthreads();
    for (int s = 0; s < 4; s++) {
        float4 p[4];
        if (s < 3) wload(Wg, 32 * (s + 1), tid, p);
        const float* Wb = (s & 1) ? buf1 : buf0;
        const int kb = 32 * s;
#pragma unroll 2
        for (int g = 0; g < 8; g++) {
            float4 a4[8];
#pragma unroll
            for (int rr = 0; rr < 8; rr++)
                a4[rr] = *(const float4*)(A + (r0 + rr) * 128 + kb + 4 * g);
            const float* wrow = Wb + (4 * g) * 128 + c0;
#pragma unroll
            for (int kkk = 0; kkk < 4; kkk++) {
                float4 w0 = *(const float4*)(wrow + kkk * 128);
                float4 w1 = *(const float4*)(wrow + kkk * 128 + 4);
                ull wA = pack2(w0.x, w0.y), wB = pack2(w0.z, w0.w);
                ull wC = pack2(w1.x, w1.y), wD = pack2(w1.z, w1.w);
#pragma unroll
                for (int rr = 0; rr < 8; rr++) {
                    float av = (kkk == 0) ? a4[rr].x : (kkk == 1) ? a4[rr].y
                             : (kkk == 2) ? a4[rr].z : a4[rr].w;
                    ull a2 = pack2(av, av);
                    acc[rr][0] = fma2_(a2, wA, acc[rr][0]);
                    acc[rr][1] = fma2_(a2, wB, acc[rr][1]);
                    acc[rr][2] = fma2_(a2, wC, acc[rr][2]);
                    acc[rr][3] = fma2_(a2, wD, acc[rr][3]);
                }
            }
        }
        if (s < 3) wstore((s & 1) ? buf0 : buf1, tid, p);
        __syncthreads();
    }
    if (MODE == 0) {
#pragma unroll
        for (int rr = 0; rr < 8; rr++) {
            float l0, h0, l1, h1, l2, h2, l3, h3;
            unpack2(acc[rr][0], l0, h0); unpack2(acc[rr][1], l1, h1);
            unpack2(acc[rr][2], l2, h2); unpack2(acc[rr][3], l3, h3);
            *(float4*)(C + (r0 + rr) * 128 + c0)     = make_float4(l0, h0, l1, h1);
            *(float4*)(C + (r0 + rr) * 128 + c0 + 4) = make_float4(l2, h2, l3, h3);
        }
    } else {
#pragma unroll
        for (int cc = 0; cc < 4; cc++) {
            float lo[8], hi[8];
#pragma unroll
            for (int rr = 0; rr < 8; rr++) unpack2(acc[rr][cc], lo[rr], hi[rr]);
            int j = c0 + 2 * cc;
            *(float4*)(C + j * 128 + r0)     = make_float4(lo[0], lo[1], lo[2], lo[3]);
            *(float4*)(C + j * 128 + r0 + 4) = make_float4(lo[4], lo[5], lo[6], lo[7]);
            *(float4*)(C + (j + 1) * 128 + r0)     = make_float4(hi[0], hi[1], hi[2], hi[3]);
            *(float4*)(C + (j + 1) * 128 + r0 + 4) = make_float4(hi[4], hi[5], hi[6], hi[7]);
        }
    }
}

// ---------------------------------------------------------------------------
// 32x128x128 GEMM core: acc = A(32 rows, stride 128) @ Wg + bg
// 256 threads: 4 rows x 4 cols per thread. Single-buffer 32-k stages in Wbuf
// with register prefetch (LDG for next stage hidden under current compute).
// Caller must __syncthreads() before entry (Wbuf gets overwritten at top).
// ---------------------------------------------------------------------------
__device__ __forceinline__ void gemm32_core(const float* __restrict__ A,
                                            const float* __restrict__ Wg,
                                            const float* __restrict__ bg,
                                            float* Wbuf, int tid, ull acc[4][2]) {
    const int ty = tid >> 5, tx = tid & 31;
    const int r0 = 4 * ty, c0 = 4 * tx;
    {
        float4 b4 = *(const float4*)(bg + c0);
        ull b0 = pack2(b4.x, b4.y), b1 = pack2(b4.z, b4.w);
#pragma unroll
        for (int rr = 0; rr < 4; rr++) { acc[rr][0] = b0; acc[rr][1] = b1; }
    }
    {
        float4 p[4];
        wload(Wg, 0, tid, p);
        wstore(Wbuf, tid, p);
    }
    __syncthreads();
    for (int s = 0; s < 4; s++) {
        float4 p[4];
        if (s < 3) wload(Wg, 32 * (s + 1), tid, p);
        const int kb = 32 * s;
#pragma unroll 4
        for (int g = 0; g < 8; g++) {
            float4 a4[4];
#pragma unroll
            for (int rr = 0; rr < 4; rr++)
                a4[rr] = *(const float4*)(A + (r0 + rr) * 128 + kb + 4 * g);
#pragma unroll
            for (int kkk = 0; kkk < 4; kkk++) {
                float4 w4 = *(const float4*)(Wbuf + (4 * g + kkk) * 128 + c0);
                ull wA = pack2(w4.x, w4.y), wB = pack2(w4.z, w4.w);
#pragma unroll
                for (int rr = 0; rr < 4; rr++) {
                    float av = (kkk == 0) ? a4[rr].x : (kkk == 1) ? a4[rr].y
                             : (kkk == 2) ? a4[rr].z : a4[rr].w;
                    ull a2 = pack2(av, av);
                    acc[rr][0] = fma2_(a2, wA, acc[rr][0]);
                    acc[rr][1] = fma2_(a2, wB, acc[rr][1]);
                }
            }
        }
        __syncthreads();                       // readers of Wbuf done
        if (s < 3) { wstore(Wbuf, tid, p); __syncthreads(); }
    }
}

// acc = A(32 rows) @ Bm(smem [128][128]); no bias, no staging.
__device__ __forceinline__ void gemm_sv_core(const float* __restrict__ A,
                                             const float* __restrict__ Bm,
                                             int tid, ull acc[4][2]) {
    const int ty = tid >> 5, tx = tid & 31;
    const int r0 = 4 * ty, c0 = 4 * tx;
#pragma unroll
    for (int rr = 0; rr < 4; rr++) { acc[rr][0] = 0ull; acc[rr][1] = 0ull; }
#pragma unroll 4
    for (int g = 0; g < 32; g++) {
        float4 a4[4];
#pragma unroll
        for (int rr = 0; rr < 4; rr++)
            a4[rr] = *(const float4*)(A + (r0 + rr) * 128 + 4 * g);
#pragma unroll
        for (int kkk = 0; kkk < 4; kkk++) {
            float4 w4 = *(const float4*)(Bm + (4 * g + kkk) * 128 + c0);
            ull wA = pack2(w4.x, w4.y), wB = pack2(w4.z, w4.w);
#pragma unroll
            for (int rr = 0; rr < 4; rr++) {
                float av = (kkk == 0) ? a4[rr].x : (kkk == 1) ? a4[rr].y
                         : (kkk == 2) ? a4[rr].z : a4[rr].w;
                ull a2 = pack2(av, av);
                acc[rr][0] = fma2_(a2, wA, acc[rr][0]);
                acc[rr][1] = fma2_(a2, wB, acc[rr][1]);
            }
        }
    }
}

__device__ __forceinline__ void store_acc32(ull acc[4][2], float* C, int tid,
                                            float scale, bool relu) {
    const int ty = tid >> 5, tx = tid & 31;
    const int r0 = 4 * ty, c0 = 4 * tx;
#pragma unroll
    for (int rr = 0; rr < 4; rr++) {
        float l0, h0, l1, h1;
        unpack2(acc[rr][0], l0, h0);
        unpack2(acc[rr][1], l1, h1);
        l0 *= scale; h0 *= scale; l1 *= scale; h1 *= scale;
        if (relu) {
            l0 = fmaxf(l0, 0.0f); h0 = fmaxf(h0, 0.0f);
            l1 = fmaxf(l1, 0.0f); h1 = fmaxf(h1, 0.0f);
        }
        *(float4*)(C + (r0 + rr) * 128 + c0) = make_float4(l0, h0, l1, h1);
    }
}

// Causal softmax on S[32][128] (rows are tokens c0chunk + lr).
__device__ void softmax32(float* S, int c0, int tid) {
    const int w = tid >> 5, lane = tid & 31;
#pragma unroll
    for (int i = 0; i < 4; i++) {
        int lr = 4 * w + i;
        int t = c0 + lr;
        float e[4];
        float mx = -3.0e38f;
#pragma unroll
        for (int q = 0; q < 4; q++) {
            int j = lane + 32 * q;
            float v = (j <= t) ? S[lr * 128 + j] : -3.0e38f;
            e[q] = v;
            mx = fmaxf(mx, v);
        }
        mx = warp_max(mx);
        float sum = 0.0f;
#pragma unroll
        for (int q = 0; q < 4; q++) {
            int j = lane + 32 * q;
            float p = (j <= t) ? __expf(e[q] - mx) : 0.0f;
            e[q] = p;
            sum += p;
        }
        sum = warp_sum(sum);
        float inv = 1.0f / sum;
#pragma unroll
        for (int q = 0; q < 4; q++) {
            int j = lane + 32 * q;
            S[lr * 128 + j] = e[q] * inv;
        }
    }
}

// acc + residual(base row from R) -> LayerNorm -> store (either smem or gmem).
__device__ __forceinline__ void ln_epilogue(ull acc[4][2], const float* R,
                                            float* dst, size_t dstride, int c0,
                                            int tid) {
    const int ty = tid >> 5, tx = tid & 31;
#pragma unroll
    for (int rr = 0; rr < 4; rr++) {
        int r = c0 + 4 * ty + rr;
        float4 x4 = *(const float4*)(R + r * 128 + 4 * tx);
        float e0, e1, e2, e3;
        unpack2(acc[rr][0], e0, e1);
        unpack2(acc[rr][1], e2, e3);
        e0 += x4.x; e1 += x4.y; e2 += x4.z; e3 += x4.w;
        float s = warp_sum(e0 + e1 + e2 + e3);
        float mu = s * (1.0f / 128.0f);
        e0 -= mu; e1 -= mu; e2 -= mu; e3 -= mu;
        float q = warp_sum(e0 * e0 + e1 * e1 + e2 * e2 + e3 * e3);
        float inv = rsqrtf(q * (1.0f / 128.0f) + 1e-5f);
        *(float4*)(dst + (size_t)r * dstride + 4 * tx) =
            make_float4(e0 * inv, e1 * inv, e2 * inv, e3 * inv);
    }
}

__global__ void __launch_bounds__(256, 1)
fused_tattn(const float* __restrict__ x, const float* __restrict__ te,
            const float* __restrict__ wq, const float* __restrict__ bq,
            const float* __restrict__ wk, const float* __restrict__ bk,
            const float* __restrict__ wv, const float* __restrict__ bv,
            const float* __restrict__ wo, const float* __restrict__ bo,
            const float* __restrict__ w1, const float* __restrict__ b1,
            const float* __restrict__ w2, const float* __restrict__ b2,
            float* __restrict__ out) {
    extern __shared__ float sm[];
    float* Xs  = sm;
    float* KsT = sm + OFF_KT;
    float* Vs  = sm + OFF_V;
    float* B1s = sm + OFF_B1;
    float* B2s = sm + OFF_B2;

    const int tid = threadIdx.x;
    const int bn = blockIdx.x;
    const int b = bn >> 8;
    const int n = bn & 255;

    const size_t tstride = (size_t)NN * NF;
    const float* xb = x + (size_t)b * NT * tstride + (size_t)n * NF;
    const float* tb = te + (size_t)b * NT * tstride + (size_t)n * NF;

    // X = x + te
#pragma unroll
    for (int i = 0; i < 16; i++) {
        int e = tid + 256 * i;          // 4096 float4s
        int t = e >> 5, f4 = e & 31;
        float4 a = *(const float4*)(xb + (size_t)t * tstride + f4 * 4);
        float4 c = *(const float4*)(tb + (size_t)t * tstride + f4 * 4);
        a.x += c.x; a.y += c.y; a.z += c.z; a.w += c.w;
        *(float4*)(Xs + t * 128 + f4 * 4) = a;
    }
    __syncthreads();

    // K (transposed into KsT) and V projections, double-buffered via B1/B2
    gemm128<1>(Xs, wk, bk, KsT, B1s, B2s, tid);
    gemm128<0>(Xs, wv, bv, Vs, B1s, B2s, tid);

    float* outbn = out + (size_t)b * NT * tstride + (size_t)n * NF;

    for (int c = 0; c < 4; c++) {
        const int c0 = 32 * c;
        const float* Ac = Xs + c0 * 128;

        {   // Q projection -> B1
            ull acc[4][2];
            gemm32_core(Ac, wq, bq, B2s, tid, acc);
            store_acc32(acc, B1s, tid, 1.0f, false);
        }
        __syncthreads();
        {   // scores S = 0.25 * Q @ K^T  -> B2
            ull acc[4][2];
            gemm_sv_core(B1s, KsT, tid, acc);
            store_acc32(acc, B2s, tid, 0.25f, false);
        }
        __syncthreads();
        softmax32(B2s, c0, tid);
        __syncthreads();
        {   // AO = P @ V -> B1
            ull acc[4][2];
            gemm_sv_core(B2s, Vs, tid, acc);
            store_acc32(acc, B1s, tid, 1.0f, false);
        }
        __syncthreads();
        {   // O-proj + residual + LN -> Xs rows
            ull acc[4][2];
            gemm32_core(B1s, wo, bo, B2s, tid, acc);
            ln_epilogue(acc, Xs, Xs, 128, c0, tid);
        }
        __syncthreads();
        {   // FFN1 (relu) -> B1
            ull acc[4][2];
            gemm32_core(Ac, w1, b1, B2s, tid, acc);
            store_acc32(acc, B1s, tid, 1.0f, true);
        }
        __syncthreads();
        {   // FFN2 + residual + LN -> global out
            ull acc[4][2];
            gemm32_core(B1s, w2, b2, B2s, tid, acc);
            ln_epilogue(acc, Xs, outbn, tstride, c0, tid);
        }
        __syncthreads();
    }
}

extern "C" void kernel_launch(void* const* d_in, const int* in_sizes, int n_in,
                              void* d_out, int out_size) {
    const float* x  = (const float*)d_in[0];
    const float* te = (const float*)d_in[1];
    const float* wq = (const float*)d_in[2];
    const float* bq = (const float*)d_in[3];
    const float* wk = (const float*)d_in[4];
    const float* bk = (const float*)d_in[5];
    const float* wv = (const float*)d_in[6];
    const float* bv = (const float*)d_in[7];
    const float* wo = (const float*)d_in[8];
    const float* bo = (const float*)d_in[9];
    const float* w1 = (const float*)d_in[10];
    const float* b1 = (const float*)d_in[11];
    const float* w2 = (const float*)d_in[12];
    const float* b2 = (const float*)d_in[13];
    float* out = (float*)d_out;

    const int smem = SMEM_FLOATS * (int)sizeof(float);  // 229376 bytes
    cudaFuncSetAttribute(fused_tattn, cudaFuncAttributeMaxDynamicSharedMemorySize, smem);
    fused_tattn<<<NB * NN, 256, smem>>>(x, te, wq, bq, wk, bk, wv, bv,
                                        wo, bo, w1, b1, w2, b2, out);
}

// round 6
// speedup vs baseline: 1.5551x; 1.0634x over previous
#include <cuda_runtime.h>
#include <cuda_bf16.h>
#include <cstdint>

#define TSTRIDE 32768

// Weight images: [wk, wq, wv, wo, w1, w2], each = [hi 32KB | lo 32KB],
// layout: row n (=f_out) * 256B, 16 chunks of 16B, chunk c stored at
// swizzled position ((c ^ (row&7)) & 7) | (c & 8).
__device__ __align__(16) unsigned char g_w[6][65536];

#define SWC(c, r7) ((uint32_t)(((((c) ^ (r7)) & 7) | ((c) & 8)) << 4))

__device__ __forceinline__ uint32_t smem_u32(const void* p) {
    uint32_t a;
    asm("{ .reg .u64 t; cvta.to.shared.u64 t, %1; cvt.u32.u64 %0, t; }" : "=r"(a) : "l"(p));
    return a;
}
// pack: low half = a, high half = b
__device__ __forceinline__ uint32_t f2bf2(float a, float b) {
    uint32_t r;
    asm("cvt.rn.bf16x2.f32 %0, %1, %2;" : "=r"(r) : "f"(b), "f"(a));
    return r;
}
__device__ __forceinline__ float2 bf2f2(uint32_t u) {
    __nv_bfloat162 h = *reinterpret_cast<__nv_bfloat162*>(&u);
    return __bfloat1622float2(h);
}
__device__ __forceinline__ void ldsm4(uint32_t* r, uint32_t a) {
    asm volatile("ldmatrix.sync.aligned.m8n8.x4.shared.b16 {%0,%1,%2,%3}, [%4];"
        : "=r"(r[0]), "=r"(r[1]), "=r"(r[2]), "=r"(r[3]) : "r"(a));
}
__device__ __forceinline__ void mma_bf16(float* d, const uint32_t* a, uint32_t b0, uint32_t b1) {
    asm volatile("mma.sync.aligned.m16n8k16.row.col.f32.bf16.bf16.f32 "
        "{%0,%1,%2,%3}, {%4,%5,%6,%7}, {%8,%9}, {%0,%1,%2,%3};"
        : "+f"(d[0]), "+f"(d[1]), "+f"(d[2]), "+f"(d[3])
        : "r"(a[0]), "r"(a[1]), "r"(a[2]), "r"(a[3]), "r"(b0), "r"(b1));
}
#define STS32(a, v)  asm volatile("st.shared.b32 [%0], %1;" :: "r"(a), "r"(v) : "memory")
#define STS128(a, v0, v1, v2, v3) \
    asm volatile("st.shared.v4.b32 [%0], {%1,%2,%3,%4};" \
        :: "r"(a), "r"(v0), "r"(v1), "r"(v2), "r"(v3) : "memory")
#define LDS32(v, a)  asm volatile("ld.shared.b32 %0, [%1];" : "=r"(v) : "r"(a))
#define STS64F(a, x, y) asm volatile("st.shared.v2.f32 [%0], {%1,%2};" :: "r"(a), "f"(x), "f"(y) : "memory")
#define LDS64F(x, y, a) asm volatile("ld.shared.v2.f32 {%0,%1}, [%2];" : "=f"(x), "=f"(y) : "r"(a))

// ============ prep kernel: W -> W^T, bf16 split, swizzled image ============
__global__ void prep_w(const float* __restrict__ wk, const float* __restrict__ wq,
                       const float* __restrict__ wv, const float* __restrict__ wo,
                       const float* __restrict__ w1, const float* __restrict__ w2) {
    const float* ws[6] = {wk, wq, wv, wo, w1, w2};
    const float* src = ws[blockIdx.x];
    unsigned char* dst = g_w[blockIdx.x];
    for (int e = threadIdx.x; e < 16384; e += blockDim.x) {
        int f = e >> 7, k = e & 127;
        float val = src[k * 128 + f];            // W^T[f][k]
        __nv_bfloat16 h = __float2bfloat16(val);
        __nv_bfloat16 l = __float2bfloat16(val - __bfloat162float(h));
        uint32_t off = (uint32_t)f * 256 + SWC(k >> 3, f & 7) + (uint32_t)(k & 7) * 2;
        *(__nv_bfloat16*)(dst + off) = h;
        *(__nv_bfloat16*)(dst + 32768 + off) = l;
    }
}

// ============ device helpers ============
// One GEMM pass: acc[128x128 per-CTA] += A(frags) @ B(image at bbase).
// Per warp: 16 rows, full N=128 (16 n8 tiles; tile i -> acc[4i..4i+3]).
__device__ __forceinline__ void gpass(uint32_t bbase, const uint32_t* af, float* acc,
                                      int noff, int khalf) {
    const int rr = noff & 7;
#pragma unroll
    for (int j = 0; j < 8; j++) {
        const uint32_t* a = af + 4 * j;
        const uint32_t csw = SWC(2 * j + khalf, rr);
#pragma unroll
        for (int t = 0; t < 8; t++) {
            uint32_t bfr[4];
            ldsm4(bfr, bbase + (uint32_t)((16 * t + noff) * 256) + csw);
            mma_bf16(acc + 8 * t,     a, bfr[0], bfr[2]);
            mma_bf16(acc + 8 * t + 4, a, bfr[1], bfr[3]);
        }
    }
}

// Load A fragments (16 rows starting at m0) from an image.
__device__ __forceinline__ void lda(uint32_t ibase, int m0, int noff, int khalf, uint32_t* af) {
    const int rr = noff & 7;
#pragma unroll
    for (int j = 0; j < 8; j++)
        ldsm4(af + 4 * j, ibase + (uint32_t)((m0 + noff) * 256) + SWC(2 * j + khalf, rr));
}

// Convert accumulator (this warp's 16x128 tile) to hi/lo A-fragments in regs.
__device__ __forceinline__ void a2f(const float* acc, uint32_t* fh, uint32_t* fl) {
#pragma unroll
    for (int j = 0; j < 8; j++)
#pragma unroll
        for (int h = 0; h < 4; h++) {
            int off = 4 * (2 * j + (h >> 1)) + 2 * (h & 1);
            float a = acc[off], b = acc[off + 1];
            uint32_t H = f2bf2(a, b);
            float2 hf = bf2f2(H);
            fh[4 * j + h] = H;
            fl[4 * j + h] = f2bf2(a - hf.x, b - hf.y);
        }
}

// Store acc tile (rows r0, r0+8) as hi/lo bf16 image rows.
__device__ __forceinline__ void simg(uint32_t ibase, const float* acc, int r0, int g, int q) {
#pragma unroll
    for (int i = 0; i < 16; i++) {
        uint32_t a0 = ibase + (uint32_t)(r0 * 256) + SWC(i, g) + 4 * q;
        float x0 = acc[4 * i], x1 = acc[4 * i + 1], x2 = acc[4 * i + 2], x3 = acc[4 * i + 3];
        uint32_t h0 = f2bf2(x0, x1), h1 = f2bf2(x2, x3);
        float2 f0 = bf2f2(h0), f1 = bf2f2(h1);
        uint32_t l0 = f2bf2(x0 - f0.x, x1 - f0.y), l1 = f2bf2(x2 - f1.x, x3 - f1.y);
        STS32(a0, h0);        STS32(a0 + 32768, l0);
        STS32(a0 + 2048, h1); STS32(a0 + 2048 + 32768, l1);
    }
}

// Stage 32KB weight half into W buffer (sync before + after).
__device__ __forceinline__ void stage(const unsigned char* src, char* wbuf, int tid) {
    __syncthreads();
    const uint4* s = (const uint4*)src;
    uint4* d = (uint4*)wbuf;
#pragma unroll
    for (int i = 0; i < 8; i++) d[tid + 256 * i] = s[tid + 256 * i];
    __syncthreads();
}

__device__ __forceinline__ void zacc(float* acc) {
#pragma unroll
    for (int i = 0; i < 64; i++) acc[i] = 0.0f;
}

__device__ __forceinline__ void biasc(float* acc, const float* __restrict__ bias, int q) {
#pragma unroll
    for (int i = 0; i < 16; i++) {
        float2 bb = __ldg((const float2*)(bias + 8 * i + 2 * q));
        acc[4 * i] += bb.x; acc[4 * i + 1] += bb.y;
        acc[4 * i + 2] += bb.x; acc[4 * i + 3] += bb.y;
    }
}

// Row-wise LayerNorm over 128 cols; rows split across 4 lanes (xor 1,2).
__device__ __forceinline__ void lnorm(float* acc) {
    float s0 = 0, s1 = 0;
#pragma unroll
    for (int i = 0; i < 16; i++) { s0 += acc[4*i] + acc[4*i+1]; s1 += acc[4*i+2] + acc[4*i+3]; }
    s0 += __shfl_xor_sync(0xffffffffu, s0, 1); s0 += __shfl_xor_sync(0xffffffffu, s0, 2);
    s1 += __shfl_xor_sync(0xffffffffu, s1, 1); s1 += __shfl_xor_sync(0xffffffffu, s1, 2);
    float mu0 = s0 * 0.0078125f, mu1 = s1 * 0.0078125f;
    float q0 = 0, q1 = 0;
#pragma unroll
    for (int i = 0; i < 16; i++) {
        acc[4*i] -= mu0; acc[4*i+1] -= mu0; acc[4*i+2] -= mu1; acc[4*i+3] -= mu1;
        q0 += acc[4*i]*acc[4*i] + acc[4*i+1]*acc[4*i+1];
        q1 += acc[4*i+2]*acc[4*i+2] + acc[4*i+3]*acc[4*i+3];
    }
    q0 += __shfl_xor_sync(0xffffffffu, q0, 1); q0 += __shfl_xor_sync(0xffffffffu, q0, 2);
    q1 += __shfl_xor_sync(0xffffffffu, q1, 1); q1 += __shfl_xor_sync(0xffffffffu, q1, 2);
    float i0 = rsqrtf(q0 * 0.0078125f + 1e-5f), i1 = rsqrtf(q1 * 0.0078125f + 1e-5f);
#pragma unroll
    for (int i = 0; i < 16; i++) {
        acc[4*i] *= i0; acc[4*i+1] *= i0; acc[4*i+2] *= i1; acc[4*i+3] *= i1;
    }
}

// ============ main fused kernel ============
// smem: [BA: X hi/lo images 64KB][BB: K hi/lo -> later U fp32 64KB]
//       [BC: V^T hi/lo 64KB][WB: weight staging 32KB]  total 229376 B
__global__ void __launch_bounds__(256, 1)
fused_hmma(const float* __restrict__ x, const float* __restrict__ te,
           const float* __restrict__ bq, const float* __restrict__ bk,
           const float* __restrict__ bv, const float* __restrict__ bo,
           const float* __restrict__ b1, const float* __restrict__ b2,
           float* __restrict__ out) {
    extern __shared__ char smc[];
    const uint32_t sb = smem_u32(smc);
    const uint32_t BA = sb, BB = sb + 65536, BC = sb + 131072, WB = sb + 196608;
    char* WBc = smc + 196608;

    const int tid = threadIdx.x, lane = tid & 31, w = tid >> 5;
    const int g = lane >> 2, q = lane & 3;
    const int m0 = 16 * w;
    const int noff = ((lane >> 3) & 1) * 8 + (lane & 7);
    const int khalf = lane >> 4;
    const int r0 = m0 + g, r1 = r0 + 8;

    const int bn = blockIdx.x, b = bn >> 8, n = bn & 255;
    const float* xb  = x  + (size_t)b * 128 * TSTRIDE + (size_t)n * 128;
    const float* teb = te + (size_t)b * 128 * TSTRIDE + (size_t)n * 128;
    float* ob = out + (size_t)b * 128 * TSTRIDE + (size_t)n * 128;

    // ---- build X = x + te hi/lo swizzled images ----
    {
        int row = tid >> 1, half = tid & 1;
        const float4* xr = (const float4*)(xb  + (size_t)row * TSTRIDE + 64 * half);
        const float4* tr = (const float4*)(teb + (size_t)row * TSTRIDE + 64 * half);
#pragma unroll
        for (int ci = 0; ci < 8; ci++) {
            float4 a = xr[2 * ci],     c = tr[2 * ci];
            float4 a2 = xr[2 * ci + 1], c2 = tr[2 * ci + 1];
            float v0 = a.x + c.x, v1 = a.y + c.y, v2 = a.z + c.z, v3 = a.w + c.w;
            float v4 = a2.x + c2.x, v5 = a2.y + c2.y, v6 = a2.z + c2.z, v7 = a2.w + c2.w;
            uint32_t h0 = f2bf2(v0, v1), h1 = f2bf2(v2, v3);
            uint32_t h2 = f2bf2(v4, v5), h3 = f2bf2(v6, v7);
            float2 e0 = bf2f2(h0), e1 = bf2f2(h1), e2 = bf2f2(h2), e3 = bf2f2(h3);
            uint32_t l0 = f2bf2(v0 - e0.x, v1 - e0.y), l1 = f2bf2(v2 - e1.x, v3 - e1.y);
            uint32_t l2 = f2bf2(v4 - e2.x, v5 - e2.y), l3 = f2bf2(v6 - e3.x, v7 - e3.y);
            uint32_t addr = BA + (uint32_t)row * 256 + SWC(8 * half + ci, row & 7);
            STS128(addr, h0, h1, h2, h3);
            STS128(addr + 32768, l0, l1, l2, l3);
        }
    }
    __syncthreads();

    float acc[64];
    uint32_t fh[32], fl[32];

    // ---- K = X @ Wk -> BB image ----
    {
        uint32_t xh[32], xl[32];
        lda(BA, m0, noff, khalf, xh);
        lda(BA + 32768, m0, noff, khalf, xl);
        stage(g_w[0], WBc, tid);
        zacc(acc);
        gpass(WB, xh, acc, noff, khalf);
        gpass(WB, xl, acc, noff, khalf);
        stage(g_w[0] + 32768, WBc, tid);
        gpass(WB, xh, acc, noff, khalf);
        biasc(acc, bk, q);
        simg(BB, acc, r0, g, q);
    }

    // ---- Q = X @ Wq -> fragments ----
    {
        uint32_t xh[32], xl[32];
        lda(BA, m0, noff, khalf, xh);
        lda(BA + 32768, m0, noff, khalf, xl);
        stage(g_w[1], WBc, tid);
        zacc(acc);
        gpass(WB, xh, acc, noff, khalf);
        gpass(WB, xl, acc, noff, khalf);
        stage(g_w[1] + 32768, WBc, tid);
        gpass(WB, xh, acc, noff, khalf);
        biasc(acc, bq, q);
        a2f(acc, fh, fl);                    // fh/fl = Q
    }

    // ---- V^T = Wv^T @ X -> BC image (A staged, B = X images) ----
    {
        uint32_t av[32];
        stage(g_w[2], WBc, tid);
        lda(WB, m0, noff, khalf, av);
        zacc(acc);
        gpass(BA, av, acc, noff, khalf);          // Ah @ Xh
        gpass(BA + 32768, av, acc, noff, khalf);  // Ah @ Xl
        stage(g_w[2] + 32768, WBc, tid);
        lda(WB, m0, noff, khalf, av);
        gpass(BA, av, acc, noff, khalf);          // Al @ Xh
        float bv0 = __ldg(bv + r0), bv1 = __ldg(bv + r1);
#pragma unroll
        for (int i = 0; i < 16; i++) {
            acc[4*i] += bv0; acc[4*i+1] += bv0; acc[4*i+2] += bv1; acc[4*i+3] += bv1;
        }
        simg(BC, acc, r0, g, q);
    }
    __syncthreads();   // BC (and BB) complete before S/AV

    // ---- S = 0.25 * Q @ K^T, causal softmax -> P fragments ----
    {
        zacc(acc);
        gpass(BB, fh, acc, noff, khalf);
        gpass(BB + 32768, fh, acc, noff, khalf);
        gpass(BB, fl, acc, noff, khalf);
        float mx0 = -3e38f, mx1 = -3e38f;
#pragma unroll
        for (int i = 0; i < 16; i++) {
            int c0 = 8 * i + 2 * q;
            float v0 = (c0     <= r0) ? acc[4*i]   * 0.25f : -3e38f;
            float v1 = (c0 + 1 <= r0) ? acc[4*i+1] * 0.25f : -3e38f;
            float v2 = (c0     <= r1) ? acc[4*i+2] * 0.25f : -3e38f;
            float v3 = (c0 + 1 <= r1) ? acc[4*i+3] * 0.25f : -3e38f;
            acc[4*i] = v0; acc[4*i+1] = v1; acc[4*i+2] = v2; acc[4*i+3] = v3;
            mx0 = fmaxf(mx0, fmaxf(v0, v1)); mx1 = fmaxf(mx1, fmaxf(v2, v3));
        }
        mx0 = fmaxf(mx0, __shfl_xor_sync(0xffffffffu, mx0, 1));
        mx0 = fmaxf(mx0, __shfl_xor_sync(0xffffffffu, mx0, 2));
        mx1 = fmaxf(mx1, __shfl_xor_sync(0xffffffffu, mx1, 1));
        mx1 = fmaxf(mx1, __shfl_xor_sync(0xffffffffu, mx1, 2));
        float s0 = 0, s1 = 0;
#pragma unroll
        for (int i = 0; i < 16; i++) {
            int c0 = 8 * i + 2 * q;
            float p0 = (c0     <= r0) ? __expf(acc[4*i]   - mx0) : 0.0f;
            float p1 = (c0 + 1 <= r0) ? __expf(acc[4*i+1] - mx0) : 0.0f;
            float p2 = (c0     <= r1) ? __expf(acc[4*i+2] - mx1) : 0.0f;
            float p3 = (c0 + 1 <= r1) ? __expf(acc[4*i+3] - mx1) : 0.0f;
            acc[4*i] = p0; acc[4*i+1] = p1; acc[4*i+2] = p2; acc[4*i+3] = p3;
            s0 += p0 + p1; s1 += p2 + p3;
        }
        s0 += __shfl_xor_sync(0xffffffffu, s0, 1); s0 += __shfl_xor_sync(0xffffffffu, s0, 2);
        s1 += __shfl_xor_sync(0xffffffffu, s1, 1); s1 += __shfl_xor_sync(0xffffffffu, s1, 2);
        float i0 = 1.0f / s0, i1 = 1.0f / s1;
#pragma unroll
        for (int i = 0; i < 16; i++) {
            acc[4*i] *= i0; acc[4*i+1] *= i0; acc[4*i+2] *= i1; acc[4*i+3] *= i1;
        }
        a2f(acc, fh, fl);                    // fh/fl = P
    }

    // ---- AO = P @ V (B = V^T image) ----
    zacc(acc);
    gpass(BC, fh, acc, noff, khalf);
    gpass(BC + 32768, fh, acc, noff, khalf);
    gpass(BC, fl, acc, noff, khalf);
    a2f(acc, fh, fl);                        // fh/fl = AO

    // ---- U = LN(AO @ Wo + bo + X) ----
    stage(g_w[3], WBc, tid);
    zacc(acc);
    gpass(WB, fh, acc, noff, khalf);
    gpass(WB, fl, acc, noff, khalf);
    stage(g_w[3] + 32768, WBc, tid);
    gpass(WB, fh, acc, noff, khalf);
    biasc(acc, bo, q);
#pragma unroll
    for (int i = 0; i < 16; i++) {           // + X residual (hi+lo reconstruct)
        uint32_t a0 = BA + (uint32_t)(r0 * 256) + SWC(i, g) + 4 * q;
        uint32_t h, l;
        LDS32(h, a0); LDS32(l, a0 + 32768);
        float2 hf = bf2f2(h), lf = bf2f2(l);
        acc[4*i] += hf.x + lf.x; acc[4*i+1] += hf.y + lf.y;
        LDS32(h, a0 + 2048); LDS32(l, a0 + 2048 + 32768);
        hf = bf2f2(h); lf = bf2f2(l);
        acc[4*i+2] += hf.x + lf.x; acc[4*i+3] += hf.y + lf.y;
    }
    lnorm(acc);
#pragma unroll
    for (int i = 0; i < 16; i++) {           // store U fp32 into BB (warp-private rows)
        uint32_t a0 = BB + (uint32_t)(r0 * 512) + (uint32_t)(8 * i + 2 * q) * 4;
        STS64F(a0, acc[4*i], acc[4*i+1]);
        STS64F(a0 + 4096, acc[4*i+2], acc[4*i+3]);
    }
    a2f(acc, fh, fl);                        // fh/fl = U

    // ---- H = relu(U @ W1 + b1) ----
    stage(g_w[4], WBc, tid);
    zacc(acc);
    gpass(WB, fh, acc, noff, khalf);
    gpass(WB, fl, acc, noff, khalf);
    stage(g_w[4] + 32768, WBc, tid);
    gpass(WB, fh, acc, noff, khalf);
    biasc(acc, b1, q);
#pragma unroll
    for (int i = 0; i < 64; i++) acc[i] = fmaxf(acc[i], 0.0f);
    a2f(acc, fh, fl);                        // fh/fl = H

    // ---- out = LN(H @ W2 + b2 + U) ----
    stage(g_w[5], WBc, tid);
    zacc(acc);
    gpass(WB, fh, acc, noff, khalf);
    gpass(WB, fl, acc, noff, khalf);
    stage(g_w[5] + 32768, WBc, tid);
    gpass(WB, fh, acc, noff, khalf);
    biasc(acc, b2, q);
#pragma unroll
    for (int i = 0; i < 16; i++) {           // + U residual
        uint32_t a0 = BB + (uint32_t)(r0 * 512) + (uint32_t)(8 * i + 2 * q) * 4;
        float ux, uy;
        LDS64F(ux, uy, a0);
        acc[4*i] += ux; acc[4*i+1] += uy;
        LDS64F(ux, uy, a0 + 4096);
        acc[4*i+2] += ux; acc[4*i+3] += uy;
    }
    lnorm(acc);
#pragma unroll
    for (int i = 0; i < 16; i++) {
        *(float2*)(ob + (size_t)r0 * TSTRIDE + 8 * i + 2 * q) =
            make_float2(acc[4*i], acc[4*i+1]);
        *(float2*)(ob + (size_t)r1 * TSTRIDE + 8 * i + 2 * q) =
            make_float2(acc[4*i+2], acc[4*i+3]);
    }
}

extern "C" void kernel_launch(void* const* d_in, const int* in_sizes, int n_in,
                              void* d_out, int out_size) {
    const float* x  = (const float*)d_in[0];
    const float* te = (const float*)d_in[1];
    const float* wq = (const float*)d_in[2];
    const float* bq = (const float*)d_in[3];
    const float* wk = (const float*)d_in[4];
    const float* bk = (const float*)d_in[5];
    const float* wv = (const float*)d_in[6];
    const float* bv = (const float*)d_in[7];
    const float* wo = (const float*)d_in[8];
    const float* bo = (const float*)d_in[9];
    const float* w1 = (const float*)d_in[10];
    const float* b1 = (const float*)d_in[11];
    const float* w2 = (const float*)d_in[12];
    const float* b2 = (const float*)d_in[13];
    float* out = (float*)d_out;

    prep_w<<<6, 256>>>(wk, wq, wv, wo, w1, w2);
    const int smem = 229376;
    cudaFuncSetAttribute(fused_hmma, cudaFuncAttributeMaxDynamicSharedMemorySize, smem);
    fused_hmma<<<4096, 256, smem>>>(x, te, bq, bk, bv, bo, b1, b2, out);
}

// round 7
// speedup vs baseline: 2.1259x; 1.3671x over previous
#include <cuda_runtime.h>
#include <cuda_bf16.h>
#include <cstdint>

#define TSTRIDE 32768
#define THREADS 512

// smem byte offsets
#define BUF0 0u
#define BUF1 65536u
#define BUF2 131072u
#define WOFF 196608u
#define SCOFF 229376u     // SCA 256 floats | SCB 256 floats
#define SMEM_TOT 231424

// Weight images: [wk, wq, wv, wo, w1, w2], each = [hi 32KB | lo 32KB]
// row f_out * 256B, 16 chunks of 16B, chunk c at swizzled pos ((c^(row&7))&7)|(c&8)
__device__ __align__(16) unsigned char g_w[6][65536];

#define SWC(c, r7) ((uint32_t)(((((c) ^ (r7)) & 7) | ((c) & 8)) << 4))

__device__ __forceinline__ uint32_t smem_u32(const void* p) {
    uint32_t a;
    asm("{ .reg .u64 t; cvta.to.shared.u64 t, %1; cvt.u32.u64 %0, t; }" : "=r"(a) : "l"(p));
    return a;
}
__device__ __forceinline__ uint32_t f2bf2(float a, float b) {   // lo=a, hi=b
    uint32_t r;
    asm("cvt.rn.bf16x2.f32 %0, %1, %2;" : "=r"(r) : "f"(b), "f"(a));
    return r;
}
__device__ __forceinline__ float2 bf2f2(uint32_t u) {
    __nv_bfloat162 h = *reinterpret_cast<__nv_bfloat162*>(&u);
    return __bfloat1622float2(h);
}
__device__ __forceinline__ void ldsm4(uint32_t* r, uint32_t a) {
    asm volatile("ldmatrix.sync.aligned.m8n8.x4.shared.b16 {%0,%1,%2,%3}, [%4];"
        : "=r"(r[0]), "=r"(r[1]), "=r"(r[2]), "=r"(r[3]) : "r"(a));
}
__device__ __forceinline__ void mma_bf16(float* d, const uint32_t* a, uint32_t b0, uint32_t b1) {
    asm volatile("mma.sync.aligned.m16n8k16.row.col.f32.bf16.bf16.f32 "
        "{%0,%1,%2,%3}, {%4,%5,%6,%7}, {%8,%9}, {%0,%1,%2,%3};"
        : "+f"(d[0]), "+f"(d[1]), "+f"(d[2]), "+f"(d[3])
        : "r"(a[0]), "r"(a[1]), "r"(a[2]), "r"(a[3]), "r"(b0), "r"(b1));
}
#define STS32(a, v)  asm volatile("st.shared.b32 [%0], %1;" :: "r"(a), "r"(v) : "memory")
#define STS128(a, v0, v1, v2, v3) \
    asm volatile("st.shared.v4.b32 [%0], {%1,%2,%3,%4};" \
        :: "r"(a), "r"(v0), "r"(v1), "r"(v2), "r"(v3) : "memory")
#define LDS32(v, a)  asm volatile("ld.shared.b32 %0, [%1];" : "=r"(v) : "r"(a))

// ============ prep kernel (unchanged from round 6) ============
__global__ void prep_w(const float* __restrict__ wk, const float* __restrict__ wq,
                       const float* __restrict__ wv, const float* __restrict__ wo,
                       const float* __restrict__ w1, const float* __restrict__ w2) {
    const float* ws[6] = {wk, wq, wv, wo, w1, w2};
    const float* src = ws[blockIdx.x];
    unsigned char* dst = g_w[blockIdx.x];
    for (int e = threadIdx.x; e < 16384; e += blockDim.x) {
        int f = e >> 7, k = e & 127;
        float val = src[k * 128 + f];            // W^T[f][k]
        __nv_bfloat16 h = __float2bfloat16(val);
        __nv_bfloat16 l = __float2bfloat16(val - __bfloat162float(h));
        uint32_t off = (uint32_t)f * 256 + SWC(k >> 3, f & 7) + (uint32_t)(k & 7) * 2;
        *(__nv_bfloat16*)(dst + off) = h;
        *(__nv_bfloat16*)(dst + 32768 + off) = l;
    }
}

// ============ device helpers ============
// A fragments: 16 rows (m0..m0+15), full K=128 -> 32 regs
__device__ __forceinline__ void lda(uint32_t ibase, int m0, int noff, int khalf, uint32_t* af) {
    const int rr = noff & 7;
#pragma unroll
    for (int j = 0; j < 8; j++)
        ldsm4(af + 4 * j, ibase + (uint32_t)((m0 + noff) * 256) + SWC(2 * j + khalf, rr));
}

// acc(16x64 per warp) += A @ B(image); warp covers cols [64*wn, 64*wn+64)
__device__ __forceinline__ void gpass(uint32_t bbase, const uint32_t* af, float* acc,
                                      int wn, int noff, int khalf) {
    const int rr = noff & 7;
#pragma unroll
    for (int j = 0; j < 8; j++) {
        const uint32_t csw = SWC(2 * j + khalf, rr);
        const uint32_t* a = af + 4 * j;
#pragma unroll
        for (int t = 0; t < 4; t++) {
            uint32_t bfr[4];
            ldsm4(bfr, bbase + (uint32_t)((64 * wn + 16 * t + noff) * 256) + csw);
            mma_bf16(acc + 8 * t,     a, bfr[0], bfr[2]);
            mma_bf16(acc + 8 * t + 4, a, bfr[1], bfr[3]);
        }
    }
}

__device__ __forceinline__ void zacc(float* acc) {
#pragma unroll
    for (int i = 0; i < 32; i++) acc[i] = 0.0f;
}

// store acc tile rows r0,r0+8, cols 64wn.. as hi/lo bf16 image
__device__ __forceinline__ void simg(uint32_t ibase, const float* acc, int r0, int wn,
                                     int g, int q) {
#pragma unroll
    for (int i = 0; i < 8; i++) {
        uint32_t a0 = ibase + (uint32_t)(r0 * 256) + SWC(8 * wn + i, g) + 4 * q;
        float x0 = acc[4*i], x1 = acc[4*i+1], x2 = acc[4*i+2], x3 = acc[4*i+3];
        uint32_t h0 = f2bf2(x0, x1), h1 = f2bf2(x2, x3);
        float2 f0 = bf2f2(h0), f1 = bf2f2(h1);
        uint32_t l0 = f2bf2(x0 - f0.x, x1 - f0.y), l1 = f2bf2(x2 - f1.x, x3 - f1.y);
        STS32(a0, h0);        STS32(a0 + 32768, l0);
        STS32(a0 + 2048, h1); STS32(a0 + 2048 + 32768, l1);
    }
}

__device__ __forceinline__ void biasc(float* acc, const float* __restrict__ bias, int wn, int q) {
#pragma unroll
    for (int i = 0; i < 8; i++) {
        float2 bb = __ldg((const float2*)(bias + 64 * wn + 8 * i + 2 * q));
        acc[4*i] += bb.x; acc[4*i+1] += bb.y; acc[4*i+2] += bb.x; acc[4*i+3] += bb.y;
    }
}

// weight GEMM: acc = A(img) @ W (3-pass hi/lo split), lo prefetched in regs
__device__ __forceinline__ void wgemm(const unsigned char* wsrc, uint32_t W, char* Wc,
                                      uint32_t aimg, float* acc, int tid, int m0,
                                      int wn, int noff, int khalf) {
    __syncthreads();                         // W free, aimg stable
    {
        const uint4* s = (const uint4*)wsrc;
        uint4* d = (uint4*)Wc;
#pragma unroll
        for (int i = 0; i < 4; i++) d[tid + 512 * i] = s[tid + 512 * i];
    }
    uint4 p[4];
    {
        const uint4* s = (const uint4*)(wsrc + 32768);
#pragma unroll
        for (int i = 0; i < 4; i++) p[i] = s[tid + 512 * i];
    }
    __syncthreads();
    uint32_t af[32];
    zacc(acc);
    lda(aimg, m0, noff, khalf, af);
    gpass(W, af, acc, wn, noff, khalf);      // Ah @ Wh
    lda(aimg + 32768, m0, noff, khalf, af);
    gpass(W, af, acc, wn, noff, khalf);      // Al @ Wh
    __syncthreads();
    {
        uint4* d = (uint4*)Wc;
#pragma unroll
        for (int i = 0; i < 4; i++) d[tid + 512 * i] = p[i];
    }
    __syncthreads();
    lda(aimg, m0, noff, khalf, af);
    gpass(W, af, acc, wn, noff, khalf);      // Ah @ Wl
}

// ============ main kernel ============
__global__ void __launch_bounds__(THREADS, 1)
fused_hmma2(const float* __restrict__ x, const float* __restrict__ te,
            const float* __restrict__ bq, const float* __restrict__ bk,
            const float* __restrict__ bv, const float* __restrict__ bo,
            const float* __restrict__ b1, const float* __restrict__ b2,
            float* __restrict__ out) {
    extern __shared__ char smc[];
    const uint32_t sb = smem_u32(smc);
    const uint32_t B0 = sb + BUF0, B1 = sb + BUF1, B2 = sb + BUF2, W = sb + WOFF;
    char* Wc = smc + WOFF;
    float* SCA = (float*)(smc + SCOFF);
    float* SCB = SCA + 256;

    const int tid = threadIdx.x, lane = tid & 31, w = tid >> 5;
    const int wm = w >> 1, wn = w & 1;
    const int m0 = 16 * wm;
    const int g = lane >> 2, q = lane & 3;
    const int noff = ((lane >> 3) & 1) * 8 + (lane & 7);
    const int khalf = lane >> 4;
    const int r0 = m0 + g, r1 = r0 + 8;

    const int bn = blockIdx.x, b = bn >> 8, n = bn & 255;
    const float* xb  = x  + (size_t)b * 128 * TSTRIDE + (size_t)n * 128;
    const float* teb = te + (size_t)b * 128 * TSTRIDE + (size_t)n * 128;
    float* ob = out + (size_t)b * 128 * TSTRIDE + (size_t)n * 128;

    // ---- build X = x+te hi/lo image -> BUF0 ----
    {
        int row = tid >> 2, quarter = tid & 3;
        const float4* xr = (const float4*)(xb  + (size_t)row * TSTRIDE + 32 * quarter);
        const float4* tr = (const float4*)(teb + (size_t)row * TSTRIDE + 32 * quarter);
#pragma unroll
        for (int ci = 0; ci < 4; ci++) {
            float4 a = xr[2*ci], c = tr[2*ci], a2 = xr[2*ci+1], c2 = tr[2*ci+1];
            float v0 = a.x + c.x, v1 = a.y + c.y, v2 = a.z + c.z, v3 = a.w + c.w;
            float v4 = a2.x + c2.x, v5 = a2.y + c2.y, v6 = a2.z + c2.z, v7 = a2.w + c2.w;
            uint32_t h0 = f2bf2(v0, v1), h1 = f2bf2(v2, v3);
            uint32_t h2 = f2bf2(v4, v5), h3 = f2bf2(v6, v7);
            float2 e0 = bf2f2(h0), e1 = bf2f2(h1), e2 = bf2f2(h2), e3 = bf2f2(h3);
            uint32_t l0 = f2bf2(v0 - e0.x, v1 - e0.y), l1 = f2bf2(v2 - e1.x, v3 - e1.y);
            uint32_t l2 = f2bf2(v4 - e2.x, v5 - e2.y), l3 = f2bf2(v6 - e3.x, v7 - e3.y);
            uint32_t addr = B0 + (uint32_t)row * 256 + SWC(4 * quarter + ci, row & 7);
            STS128(addr, h0, h1, h2, h3);
            STS128(addr + 32768, l0, l1, l2, l3);
        }
    }

    float acc[32];

    // ---- V^T = Wv^T @ X -> BUF1 (A = staged Wv, B = X image) ----
    {
        __syncthreads();     // X image complete
        {
            const uint4* s = (const uint4*)g_w[2];
            uint4* d = (uint4*)Wc;
#pragma unroll
            for (int i = 0; i < 4; i++) d[tid + 512 * i] = s[tid + 512 * i];
        }
        uint4 p[4];
        {
            const uint4* s = (const uint4*)(g_w[2] + 32768);
#pragma unroll
            for (int i = 0; i < 4; i++) p[i] = s[tid + 512 * i];
        }
        __syncthreads();
        uint32_t af[32];
        zacc(acc);
        lda(W, m0, noff, khalf, af);
        gpass(B0, af, acc, wn, noff, khalf);           // Wh @ Xh
        gpass(B0 + 32768, af, acc, wn, noff, khalf);   // Wh @ Xl
        __syncthreads();
        {
            uint4* d = (uint4*)Wc;
#pragma unroll
            for (int i = 0; i < 4; i++) d[tid + 512 * i] = p[i];
        }
        __syncthreads();
        lda(W, m0, noff, khalf, af);
        gpass(B0, af, acc, wn, noff, khalf);           // Wl @ Xh
        float bv0 = __ldg(bv + r0), bv1 = __ldg(bv + r1);
#pragma unroll
        for (int i = 0; i < 8; i++) {
            acc[4*i] += bv0; acc[4*i+1] += bv0; acc[4*i+2] += bv1; acc[4*i+3] += bv1;
        }
        simg(B1, acc, r0, wn, g, q);
    }

    // ---- K = X @ Wk -> BUF2 ----
    wgemm(g_w[0], W, Wc, B0, acc, tid, m0, wn, noff, khalf);
    biasc(acc, bk, wn, q);
    __syncthreads();
    simg(B2, acc, r0, wn, g, q);

    // ---- Q = X @ Wq -> BUF0 (X dies; residual re-read later) ----
    wgemm(g_w[1], W, Wc, B0, acc, tid, m0, wn, noff, khalf);
    biasc(acc, bq, wn, q);
    __syncthreads();          // all X reads done
    simg(B0, acc, r0, wn, g, q);
    __syncthreads();

    // ---- S = 0.25*Q@K^T, causal softmax -> P -> BUF0 ----
    {
        uint32_t af[32];
        zacc(acc);
        lda(B0, m0, noff, khalf, af);
        gpass(B2, af, acc, wn, noff, khalf);           // Qh @ Kh
        lda(B0 + 32768, m0, noff, khalf, af);
        gpass(B2, af, acc, wn, noff, khalf);           // Ql @ Kh
        lda(B0, m0, noff, khalf, af);
        gpass(B2 + 32768, af, acc, wn, noff, khalf);   // Qh @ Kl

        float mx0 = -3e38f, mx1 = -3e38f;
#pragma unroll
        for (int i = 0; i < 8; i++) {
            int c0 = 64 * wn + 8 * i + 2 * q;
            float v0 = (c0     <= r0) ? acc[4*i]   * 0.25f : -3e38f;
            float v1 = (c0 + 1 <= r0) ? acc[4*i+1] * 0.25f : -3e38f;
            float v2 = (c0     <= r1) ? acc[4*i+2] * 0.25f : -3e38f;
            float v3 = (c0 + 1 <= r1) ? acc[4*i+3] * 0.25f : -3e38f;
            acc[4*i] = v0; acc[4*i+1] = v1; acc[4*i+2] = v2; acc[4*i+3] = v3;
            mx0 = fmaxf(mx0, fmaxf(v0, v1)); mx1 = fmaxf(mx1, fmaxf(v2, v3));
        }
        mx0 = fmaxf(mx0, __shfl_xor_sync(~0u, mx0, 1));
        mx0 = fmaxf(mx0, __shfl_xor_sync(~0u, mx0, 2));
        mx1 = fmaxf(mx1, __shfl_xor_sync(~0u, mx1, 1));
        mx1 = fmaxf(mx1, __shfl_xor_sync(~0u, mx1, 2));
        SCA[2 * r0 + wn] = mx0; SCA[2 * r1 + wn] = mx1;
        __syncthreads();
        mx0 = fmaxf(SCA[2 * r0], SCA[2 * r0 + 1]);
        mx1 = fmaxf(SCA[2 * r1], SCA[2 * r1 + 1]);
        float s0 = 0, s1 = 0;
#pragma unroll
        for (int i = 0; i < 8; i++) {
            int c0 = 64 * wn + 8 * i + 2 * q;
            float p0 = (c0     <= r0) ? __expf(acc[4*i]   - mx0) : 0.0f;
            float p1 = (c0 + 1 <= r0) ? __expf(acc[4*i+1] - mx0) : 0.0f;
            float p2 = (c0     <= r1) ? __expf(acc[4*i+2] - mx1) : 0.0f;
            float p3 = (c0 + 1 <= r1) ? __expf(acc[4*i+3] - mx1) : 0.0f;
            acc[4*i] = p0; acc[4*i+1] = p1; acc[4*i+2] = p2; acc[4*i+3] = p3;
            s0 += p0 + p1; s1 += p2 + p3;
        }
        s0 += __shfl_xor_sync(~0u, s0, 1); s0 += __shfl_xor_sync(~0u, s0, 2);
        s1 += __shfl_xor_sync(~0u, s1, 1); s1 += __shfl_xor_sync(~0u, s1, 2);
        SCB[2 * r0 + wn] = s0; SCB[2 * r1 + wn] = s1;
        __syncthreads();
        float i0 = 1.0f / (SCB[2 * r0] + SCB[2 * r0 + 1]);
        float i1 = 1.0f / (SCB[2 * r1] + SCB[2 * r1 + 1]);
#pragma unroll
        for (int i = 0; i < 8; i++) {
            acc[4*i] *= i0; acc[4*i+1] *= i0; acc[4*i+2] *= i1; acc[4*i+3] *= i1;
        }
        __syncthreads();          // all Q reads done before overwrite
        simg(B0, acc, r0, wn, g, q);
        __syncthreads();
    }

    // ---- AO = P @ V -> BUF2 (K dead) ----
    {
        uint32_t af[32];
        zacc(acc);
        lda(B0, m0, noff, khalf, af);
        gpass(B1, af, acc, wn, noff, khalf);           // Ph @ Vh
        lda(B0 + 32768, m0, noff, khalf, af);
        gpass(B1, af, acc, wn, noff, khalf);           // Pl @ Vh
        lda(B0, m0, noff, khalf, af);
        gpass(B1 + 32768, af, acc, wn, noff, khalf);   // Ph @ Vl
        __syncthreads();
        simg(B2, acc, r0, wn, g, q);
    }

    // ---- U = LN(AO @ Wo + bo + (x+te)) -> BUF0 (P dead) ----
    wgemm(g_w[3], W, Wc, B2, acc, tid, m0, wn, noff, khalf);
    biasc(acc, bo, wn, q);
#pragma unroll
    for (int i = 0; i < 8; i++) {
        int c = 64 * wn + 8 * i + 2 * q;
        float2 xa = *(const float2*)(xb + (size_t)r0 * TSTRIDE + c);
        float2 ta = *(const float2*)(teb + (size_t)r0 * TSTRIDE + c);
        acc[4*i] += xa.x + ta.x; acc[4*i+1] += xa.y + ta.y;
        float2 xc = *(const float2*)(xb + (size_t)r1 * TSTRIDE + c);
        float2 tc = *(const float2*)(teb + (size_t)r1 * TSTRIDE + c);
        acc[4*i+2] += xc.x + tc.x; acc[4*i+3] += xc.y + tc.y;
    }
    {   // LayerNorm (cross-warp via SCA/SCB)
        float s0 = 0, s1 = 0;
#pragma unroll
        for (int i = 0; i < 8; i++) { s0 += acc[4*i] + acc[4*i+1]; s1 += acc[4*i+2] + acc[4*i+3]; }
        s0 += __shfl_xor_sync(~0u, s0, 1); s0 += __shfl_xor_sync(~0u, s0, 2);
        s1 += __shfl_xor_sync(~0u, s1, 1); s1 += __shfl_xor_sync(~0u, s1, 2);
        SCA[2 * r0 + wn] = s0; SCA[2 * r1 + wn] = s1;
        __syncthreads();
        float mu0 = (SCA[2*r0] + SCA[2*r0+1]) * 0.0078125f;
        float mu1 = (SCA[2*r1] + SCA[2*r1+1]) * 0.0078125f;
        float q0 = 0, q1 = 0;
#pragma unroll
        for (int i = 0; i < 8; i++) {
            acc[4*i] -= mu0; acc[4*i+1] -= mu0; acc[4*i+2] -= mu1; acc[4*i+3] -= mu1;
            q0 += acc[4*i]*acc[4*i] + acc[4*i+1]*acc[4*i+1];
            q1 += acc[4*i+2]*acc[4*i+2] + acc[4*i+3]*acc[4*i+3];
        }
        q0 += __shfl_xor_sync(~0u, q0, 1); q0 += __shfl_xor_sync(~0u, q0, 2);
        q1 += __shfl_xor_sync(~0u, q1, 1); q1 += __shfl_xor_sync(~0u, q1, 2);
        SCB[2 * r0 + wn] = q0; SCB[2 * r1 + wn] = q1;
        __syncthreads();
        float i0 = rsqrtf((SCB[2*r0] + SCB[2*r0+1]) * 0.0078125f + 1e-5f);
        float i1 = rsqrtf((SCB[2*r1] + SCB[2*r1+1]) * 0.0078125f + 1e-5f);
#pragma unroll
        for (int i = 0; i < 8; i++) {
            acc[4*i] *= i0; acc[4*i+1] *= i0; acc[4*i+2] *= i1; acc[4*i+3] *= i1;
        }
    }
    __syncthreads();
    simg(B0, acc, r0, wn, g, q);

    // ---- H = relu(U @ W1 + b1) -> BUF2 (AO dead) ----
    wgemm(g_w[4], W, Wc, B0, acc, tid, m0, wn, noff, khalf);
    biasc(acc, b1, wn, q);
#pragma unroll
    for (int i = 0; i < 32; i++) acc[i] = fmaxf(acc[i], 0.0f);
    __syncthreads();
    simg(B2, acc, r0, wn, g, q);

    // ---- out = LN(H @ W2 + b2 + U) -> gmem ----
    wgemm(g_w[5], W, Wc, B2, acc, tid, m0, wn, noff, khalf);
    biasc(acc, b2, wn, q);
#pragma unroll
    for (int i = 0; i < 8; i++) {     // + U residual (hi+lo reconstruct from BUF0)
        uint32_t a0 = B0 + (uint32_t)(r0 * 256) + SWC(8 * wn + i, g) + 4 * q;
        uint32_t h, l;
        LDS32(h, a0); LDS32(l, a0 + 32768);
        float2 hf = bf2f2(h), lf = bf2f2(l);
        acc[4*i] += hf.x + lf.x; acc[4*i+1] += hf.y + lf.y;
        LDS32(h, a0 + 2048); LDS32(l, a0 + 2048 + 32768);
        hf = bf2f2(h); lf = bf2f2(l);
        acc[4*i+2] += hf.x + lf.x; acc[4*i+3] += hf.y + lf.y;
    }
    {   // final LayerNorm
        float s0 = 0, s1 = 0;
#pragma unroll
        for (int i = 0; i < 8; i++) { s0 += acc[4*i] + acc[4*i+1]; s1 += acc[4*i+2] + acc[4*i+3]; }
        s0 += __shfl_xor_sync(~0u, s0, 1); s0 += __shfl_xor_sync(~0u, s0, 2);
        s1 += __shfl_xor_sync(~0u, s1, 1); s1 += __shfl_xor_sync(~0u, s1, 2);
        SCA[2 * r0 + wn] = s0; SCA[2 * r1 + wn] = s1;
        __syncthreads();
        float mu0 = (SCA[2*r0] + SCA[2*r0+1]) * 0.0078125f;
        float mu1 = (SCA[2*r1] + SCA[2*r1+1]) * 0.0078125f;
        float q0 = 0, q1 = 0;
#pragma unroll
        for (int i = 0; i < 8; i++) {
            acc[4*i] -= mu0; acc[4*i+1] -= mu0; acc[4*i+2] -= mu1; acc[4*i+3] -= mu1;
            q0 += acc[4*i]*acc[4*i] + acc[4*i+1]*acc[4*i+1];
            q1 += acc[4*i+2]*acc[4*i+2] + acc[4*i+3]*acc[4*i+3];
        }
        q0 += __shfl_xor_sync(~0u, q0, 1); q0 += __shfl_xor_sync(~0u, q0, 2);
        q1 += __shfl_xor_sync(~0u, q1, 1); q1 += __shfl_xor_sync(~0u, q1, 2);
        SCB[2 * r0 + wn] = q0; SCB[2 * r1 + wn] = q1;
        __syncthreads();
        float i0 = rsqrtf((SCB[2*r0] + SCB[2*r0+1]) * 0.0078125f + 1e-5f);
        float i1 = rsqrtf((SCB[2*r1] + SCB[2*r1+1]) * 0.0078125f + 1e-5f);
#pragma unroll
        for (int i = 0; i < 8; i++) {
            int c = 64 * wn + 8 * i + 2 * q;
            *(float2*)(ob + (size_t)r0 * TSTRIDE + c) =
                make_float2(acc[4*i] * i0, acc[4*i+1] * i0);
            *(float2*)(ob + (size_t)r1 * TSTRIDE + c) =
                make_float2(acc[4*i+2] * i1, acc[4*i+3] * i1);
        }
    }
}

extern "C" void kernel_launch(void* const* d_in, const int* in_sizes, int n_in,
                              void* d_out, int out_size) {
    const float* x  = (const float*)d_in[0];
    const float* te = (const float*)d_in[1];
    const float* wq = (const float*)d_in[2];
    const float* bq = (const float*)d_in[3];
    const float* wk = (const float*)d_in[4];
    const float* bk = (const float*)d_in[5];
    const float* wv = (const float*)d_in[6];
    const float* bv = (const float*)d_in[7];
    const float* wo = (const float*)d_in[8];
    const float* bo = (const float*)d_in[9];
    const float* w1 = (const float*)d_in[10];
    const float* b1 = (const float*)d_in[11];
    const float* w2 = (const float*)d_in[12];
    const float* b2 = (const float*)d_in[13];
    float* out = (float*)d_out;

    prep_w<<<6, 256>>>(wk, wq, wv, wo, w1, w2);
    cudaFuncSetAttribute(fused_hmma2, cudaFuncAttributeMaxDynamicSharedMemorySize, SMEM_TOT);
    fused_hmma2<<<4096, THREADS, SMEM_TOT>>>(x, te, bq, bk, bv, bo, b1, b2, out);
}

// round 8
// speedup vs baseline: 3.2601x; 1.5335x over previous
#include <cuda_runtime.h>
#include <cuda_bf16.h>
#include <cstdint>

#define TSTRIDE 32768
#define THREADS 512

// smem byte offsets
#define BUF0 0u
#define BUF1 65536u
#define BUF2 131072u
#define WOFF 196608u
#define SCOFF 229376u     // SCA 256 floats | SCB 256 floats
#define SMEM_TOT 231424

// Weight images: [wk, wq, wv, wo, w1, w2], each = [hi 32KB | lo 32KB]
// row f_out * 256B, 16 chunks of 16B, chunk c at swizzled pos ((c^(row&7))&7)|(c&8)
__device__ __align__(16) unsigned char g_w[6][65536];

#define SWC(c, r7) ((uint32_t)(((((c) ^ (r7)) & 7) | ((c) & 8)) << 4))

__device__ __forceinline__ uint32_t smem_u32(const void* p) {
    uint32_t a;
    asm("{ .reg .u64 t; cvta.to.shared.u64 t, %1; cvt.u32.u64 %0, t; }" : "=r"(a) : "l"(p));
    return a;
}
__device__ __forceinline__ uint32_t f2bf2(float a, float b) {   // lo=a, hi=b
    uint32_t r;
    asm("cvt.rn.bf16x2.f32 %0, %1, %2;" : "=r"(r) : "f"(b), "f"(a));
    return r;
}
__device__ __forceinline__ float2 bf2f2(uint32_t u) {
    __nv_bfloat162 h = *reinterpret_cast<__nv_bfloat162*>(&u);
    return __bfloat1622float2(h);
}
__device__ __forceinline__ void ldsm4(uint32_t* r, uint32_t a) {
    asm volatile("ldmatrix.sync.aligned.m8n8.x4.shared.b16 {%0,%1,%2,%3}, [%4];"
        : "=r"(r[0]), "=r"(r[1]), "=r"(r[2]), "=r"(r[3]) : "r"(a));
}
__device__ __forceinline__ void mma_bf16(float* d, const uint32_t* a, uint32_t b0, uint32_t b1) {
    asm volatile("mma.sync.aligned.m16n8k16.row.col.f32.bf16.bf16.f32 "
        "{%0,%1,%2,%3}, {%4,%5,%6,%7}, {%8,%9}, {%0,%1,%2,%3};"
        : "+f"(d[0]), "+f"(d[1]), "+f"(d[2]), "+f"(d[3])
        : "r"(a[0]), "r"(a[1]), "r"(a[2]), "r"(a[3]), "r"(b0), "r"(b1));
}
#define STS32(a, v)  asm volatile("st.shared.b32 [%0], %1;" :: "r"(a), "r"(v) : "memory")
#define STS128(a, v0, v1, v2, v3) \
    asm volatile("st.shared.v4.b32 [%0], {%1,%2,%3,%4};" \
        :: "r"(a), "r"(v0), "r"(v1), "r"(v2), "r"(v3) : "memory")
#define LDS32(v, a)  asm volatile("ld.shared.b32 %0, [%1];" : "=r"(v) : "r"(a))

// ============ prep kernel ============
__global__ void prep_w(const float* __restrict__ wk, const float* __restrict__ wq,
                       const float* __restrict__ wv, const float* __restrict__ wo,
                       const float* __restrict__ w1, const float* __restrict__ w2) {
    const float* ws[6] = {wk, wq, wv, wo, w1, w2};
    const float* src = ws[blockIdx.x];
    unsigned char* dst = g_w[blockIdx.x];
    for (int e = threadIdx.x; e < 16384; e += blockDim.x) {
        int f = e >> 7, k = e & 127;
        float val = src[k * 128 + f];            // W^T[f][k]
        __nv_bfloat16 h = __float2bfloat16(val);
        __nv_bfloat16 l = __float2bfloat16(val - __bfloat162float(h));
        uint32_t off = (uint32_t)f * 256 + SWC(k >> 3, f & 7) + (uint32_t)(k & 7) * 2;
        *(__nv_bfloat16*)(dst + off) = h;
        *(__nv_bfloat16*)(dst + 32768 + off) = l;
    }
}

// ============ GEMM cores (per-k-chunk A loads, fused hi/lo) ============
// acc += Ah@Bh + Al@Bh + Ah@Bl   (all operands resident in smem)
__device__ __forceinline__ void gfused(uint32_t ahb, uint32_t alb, uint32_t bhb,
                                       uint32_t blb, float* acc, int m0, int wn,
                                       int noff, int khalf) {
    const int rr = noff & 7;
    const uint32_t arow = (uint32_t)((m0 + noff) * 256);
#pragma unroll
    for (int j = 0; j < 8; j++) {
        const uint32_t csw = SWC(2 * j + khalf, rr);
        uint32_t ah[4], al[4];
        ldsm4(ah, ahb + arow + csw);
        ldsm4(al, alb + arow + csw);
#pragma unroll
        for (int t = 0; t < 4; t++) {
            uint32_t b[4];
            ldsm4(b, bhb + (uint32_t)((64 * wn + 16 * t + noff) * 256) + csw);
            mma_bf16(acc + 8 * t,     ah, b[0], b[2]);
            mma_bf16(acc + 8 * t + 4, ah, b[1], b[3]);
            mma_bf16(acc + 8 * t,     al, b[0], b[2]);
            mma_bf16(acc + 8 * t + 4, al, b[1], b[3]);
        }
#pragma unroll
        for (int t = 0; t < 4; t++) {
            uint32_t b[4];
            ldsm4(b, blb + (uint32_t)((64 * wn + 16 * t + noff) * 256) + csw);
            mma_bf16(acc + 8 * t,     ah, b[0], b[2]);
            mma_bf16(acc + 8 * t + 4, ah, b[1], b[3]);
        }
    }
}

// acc += (Ah + Al) @ B      (single B half resident)
__device__ __forceinline__ void gAB(uint32_t ahb, uint32_t alb, uint32_t bb,
                                    float* acc, int m0, int wn, int noff, int khalf) {
    const int rr = noff & 7;
    const uint32_t arow = (uint32_t)((m0 + noff) * 256);
#pragma unroll
    for (int j = 0; j < 8; j++) {
        const uint32_t csw = SWC(2 * j + khalf, rr);
        uint32_t ah[4], al[4];
        ldsm4(ah, ahb + arow + csw);
        ldsm4(al, alb + arow + csw);
#pragma unroll
        for (int t = 0; t < 4; t++) {
            uint32_t b[4];
            ldsm4(b, bb + (uint32_t)((64 * wn + 16 * t + noff) * 256) + csw);
            mma_bf16(acc + 8 * t,     ah, b[0], b[2]);
            mma_bf16(acc + 8 * t + 4, ah, b[1], b[3]);
            mma_bf16(acc + 8 * t,     al, b[0], b[2]);
            mma_bf16(acc + 8 * t + 4, al, b[1], b[3]);
        }
    }
}

// acc += A @ B              (single A, single B half)
__device__ __forceinline__ void gA(uint32_t ab, uint32_t bb, float* acc,
                                   int m0, int wn, int noff, int khalf) {
    const int rr = noff & 7;
    const uint32_t arow = (uint32_t)((m0 + noff) * 256);
#pragma unroll
    for (int j = 0; j < 8; j++) {
        const uint32_t csw = SWC(2 * j + khalf, rr);
        uint32_t ah[4];
        ldsm4(ah, ab + arow + csw);
#pragma unroll
        for (int t = 0; t < 4; t++) {
            uint32_t b[4];
            ldsm4(b, bb + (uint32_t)((64 * wn + 16 * t + noff) * 256) + csw);
            mma_bf16(acc + 8 * t,     ah, b[0], b[2]);
            mma_bf16(acc + 8 * t + 4, ah, b[1], b[3]);
        }
    }
}

__device__ __forceinline__ void zacc(float* acc) {
#pragma unroll
    for (int i = 0; i < 32; i++) acc[i] = 0.0f;
}

// copy two 32KB halves g->smem with batched LDG (MLP=8)
__device__ __forceinline__ void stage2(const unsigned char* s1, char* d1,
                                       const unsigned char* s2, char* d2, int tid) {
    uint4 p[8];
    const uint4* a = (const uint4*)s1;
    const uint4* b = (const uint4*)s2;
#pragma unroll
    for (int i = 0; i < 4; i++) p[i] = a[tid + 512 * i];
#pragma unroll
    for (int i = 0; i < 4; i++) p[4 + i] = b[tid + 512 * i];
    uint4* da = (uint4*)d1;
    uint4* db = (uint4*)d2;
#pragma unroll
    for (int i = 0; i < 4; i++) da[tid + 512 * i] = p[i];
#pragma unroll
    for (int i = 0; i < 4; i++) db[tid + 512 * i] = p[4 + i];
}
__device__ __forceinline__ void stage1(const unsigned char* s1, char* d1, int tid) {
    uint4 p[4];
    const uint4* a = (const uint4*)s1;
#pragma unroll
    for (int i = 0; i < 4; i++) p[i] = a[tid + 512 * i];
    uint4* da = (uint4*)d1;
#pragma unroll
    for (int i = 0; i < 4; i++) da[tid + 512 * i] = p[i];
}

// store acc tile rows r0,r0+8, cols 64wn.. as hi/lo bf16 image
__device__ __forceinline__ void simg(uint32_t ibase, const float* acc, int r0, int wn,
                                     int g, int q) {
#pragma unroll
    for (int i = 0; i < 8; i++) {
        uint32_t a0 = ibase + (uint32_t)(r0 * 256) + SWC(8 * wn + i, g) + 4 * q;
        float x0 = acc[4*i], x1 = acc[4*i+1], x2 = acc[4*i+2], x3 = acc[4*i+3];
        uint32_t h0 = f2bf2(x0, x1), h1 = f2bf2(x2, x3);
        float2 f0 = bf2f2(h0), f1 = bf2f2(h1);
        uint32_t l0 = f2bf2(x0 - f0.x, x1 - f0.y), l1 = f2bf2(x2 - f1.x, x3 - f1.y);
        STS32(a0, h0);        STS32(a0 + 32768, l0);
        STS32(a0 + 2048, h1); STS32(a0 + 2048 + 32768, l1);
    }
}

__device__ __forceinline__ void biasc(float* acc, const float* __restrict__ bias, int wn, int q) {
#pragma unroll
    for (int i = 0; i < 8; i++) {
        float2 bb = __ldg((const float2*)(bias + 64 * wn + 8 * i + 2 * q));
        acc[4*i] += bb.x; acc[4*i+1] += bb.y; acc[4*i+2] += bb.x; acc[4*i+3] += bb.y;
    }
}

// ============ main kernel ============
__global__ void __launch_bounds__(THREADS, 1)
fused_hmma3(const float* __restrict__ x, const float* __restrict__ te,
            const float* __restrict__ bq, const float* __restrict__ bk,
            const float* __restrict__ bv, const float* __restrict__ bo,
            const float* __restrict__ b1, const float* __restrict__ b2,
            float* __restrict__ out) {
    extern __shared__ char smc[];
    const uint32_t sb = smem_u32(smc);
    const uint32_t B0 = sb + BUF0, B1 = sb + BUF1, B2 = sb + BUF2, W = sb + WOFF;
    char* Wc = smc + WOFF;
    float* SCA = (float*)(smc + SCOFF);
    float* SCB = SCA + 256;

    const int tid = threadIdx.x, lane = tid & 31, w = tid >> 5;
    const int wm = w >> 1, wn = w & 1;
    const int m0 = 16 * wm;
    const int g = lane >> 2, q = lane & 3;
    const int noff = ((lane >> 3) & 1) * 8 + (lane & 7);
    const int khalf = lane >> 4;
    const int r0 = m0 + g, r1 = r0 + 8;

    const int bn = blockIdx.x, b = bn >> 8, n = bn & 255;
    const float* xb  = x  + (size_t)b * 128 * TSTRIDE + (size_t)n * 128;
    const float* teb = te + (size_t)b * 128 * TSTRIDE + (size_t)n * 128;
    float* ob = out + (size_t)b * 128 * TSTRIDE + (size_t)n * 128;

    // ---- build X = x+te hi/lo image -> BUF0 ----
    {
        int row = tid >> 2, quarter = tid & 3;
        const float4* xr = (const float4*)(xb  + (size_t)row * TSTRIDE + 32 * quarter);
        const float4* tr = (const float4*)(teb + (size_t)row * TSTRIDE + 32 * quarter);
#pragma unroll
        for (int ci = 0; ci < 4; ci++) {
            float4 a = xr[2*ci], c = tr[2*ci], a2 = xr[2*ci+1], c2 = tr[2*ci+1];
            float v0 = a.x + c.x, v1 = a.y + c.y, v2 = a.z + c.z, v3 = a.w + c.w;
            float v4 = a2.x + c2.x, v5 = a2.y + c2.y, v6 = a2.z + c2.z, v7 = a2.w + c2.w;
            uint32_t h0 = f2bf2(v0, v1), h1 = f2bf2(v2, v3);
            uint32_t h2 = f2bf2(v4, v5), h3 = f2bf2(v6, v7);
            float2 e0 = bf2f2(h0), e1 = bf2f2(h1), e2 = bf2f2(h2), e3 = bf2f2(h3);
            uint32_t l0 = f2bf2(v0 - e0.x, v1 - e0.y), l1 = f2bf2(v2 - e1.x, v3 - e1.y);
            uint32_t l2 = f2bf2(v4 - e2.x, v5 - e2.y), l3 = f2bf2(v6 - e3.x, v7 - e3.y);
            uint32_t addr = B0 + (uint32_t)row * 256 + SWC(4 * quarter + ci, row & 7);
            STS128(addr, h0, h1, h2, h3);
            STS128(addr + 32768, l0, l1, l2, l3);
        }
    }

    float acc[32];

    // ==== Phase 1: V^T = Wv^T @ X -> BUF1  (A = Wv: hi in W, lo in BUF2lo) ====
    stage2(g_w[2], Wc, g_w[2] + 32768, smc + BUF2 + 32768, tid);
    __syncthreads();            // X image + staged Wv visible
    zacc(acc);
    gfused(W, B2 + 32768, B0, B0 + 32768, acc, m0, wn, noff, khalf);
    {
        float bv0 = __ldg(bv + r0), bv1 = __ldg(bv + r1);
#pragma unroll
        for (int i = 0; i < 8; i++) {
            acc[4*i] += bv0; acc[4*i+1] += bv0; acc[4*i+2] += bv1; acc[4*i+3] += bv1;
        }
    }
    simg(B1, acc, r0, wn, g, q);

    // ==== Phase 2: K = X @ Wk -> BUF2  (Wk hi in W, lo in BUF2lo) ====
    __syncthreads();            // Wv reads done before restaging
    stage2(g_w[0], Wc, g_w[0] + 32768, smc + BUF2 + 32768, tid);
    __syncthreads();
    zacc(acc);
    gfused(B0, B0 + 32768, W, B2 + 32768, acc, m0, wn, noff, khalf);
    biasc(acc, bk, wn, q);
    __syncthreads();            // Wkl reads done before simg overwrites BUF2lo
    simg(B2, acc, r0, wn, g, q);

    // ==== Phase 3: Q = X @ Wq -> BUF0  (2-phase via W buffer) ====
    __syncthreads();            // Wkh reads done
    stage1(g_w[1], Wc, tid);
    uint4 p[4];
    {
        const uint4* s = (const uint4*)(g_w[1] + 32768);
#pragma unroll
        for (int i = 0; i < 4; i++) p[i] = s[tid + 512 * i];
    }
    __syncthreads();
    zacc(acc);
    gAB(B0, B0 + 32768, W, acc, m0, wn, noff, khalf);   // (Xh+Xl)@Wqh
    __syncthreads();
    {
        uint4* d = (uint4*)Wc;
#pragma unroll
        for (int i = 0; i < 4; i++) d[tid + 512 * i] = p[i];
    }
    __syncthreads();
    gA(B0, W, acc, m0, wn, noff, khalf);                // Xh@Wql
    biasc(acc, bq, wn, q);
    __syncthreads();            // X reads done
    simg(B0, acc, r0, wn, g, q);   // Q -> BUF0
    __syncthreads();

    // ==== Phase 4: S = 0.25*Q@K^T, causal softmax -> P -> BUF0 ====
    {
        zacc(acc);
        gfused(B0, B0 + 32768, B2, B2 + 32768, acc, m0, wn, noff, khalf);
        float mx0 = -3e38f, mx1 = -3e38f;
#pragma unroll
        for (int i = 0; i < 8; i++) {
            int c0 = 64 * wn + 8 * i + 2 * q;
            float v0 = (c0     <= r0) ? acc[4*i]   * 0.25f : -3e38f;
            float v1 = (c0 + 1 <= r0) ? acc[4*i+1] * 0.25f : -3e38f;
            float v2 = (c0     <= r1) ? acc[4*i+2] * 0.25f : -3e38f;
            float v3 = (c0 + 1 <= r1) ? acc[4*i+3] * 0.25f : -3e38f;
            acc[4*i] = v0; acc[4*i+1] = v1; acc[4*i+2] = v2; acc[4*i+3] = v3;
            mx0 = fmaxf(mx0, fmaxf(v0, v1)); mx1 = fmaxf(mx1, fmaxf(v2, v3));
        }
        mx0 = fmaxf(mx0, __shfl_xor_sync(~0u, mx0, 1));
        mx0 = fmaxf(mx0, __shfl_xor_sync(~0u, mx0, 2));
        mx1 = fmaxf(mx1, __shfl_xor_sync(~0u, mx1, 1));
        mx1 = fmaxf(mx1, __shfl_xor_sync(~0u, mx1, 2));
        SCA[2 * r0 + wn] = mx0; SCA[2 * r1 + wn] = mx1;
        __syncthreads();
        mx0 = fmaxf(SCA[2 * r0], SCA[2 * r0 + 1]);
        mx1 = fmaxf(SCA[2 * r1], SCA[2 * r1 + 1]);
        float s0 = 0, s1 = 0;
#pragma unroll
        for (int i = 0; i < 8; i++) {
            int c0 = 64 * wn + 8 * i + 2 * q;
            float p0 = (c0     <= r0) ? __expf(acc[4*i]   - mx0) : 0.0f;
            float p1 = (c0 + 1 <= r0) ? __expf(acc[4*i+1] - mx0) : 0.0f;
            float p2 = (c0     <= r1) ? __expf(acc[4*i+2] - mx1) : 0.0f;
            float p3 = (c0 + 1 <= r1) ? __expf(acc[4*i+3] - mx1) : 0.0f;
            acc[4*i] = p0; acc[4*i+1] = p1; acc[4*i+2] = p2; acc[4*i+3] = p3;
            s0 += p0 + p1; s1 += p2 + p3;
        }
        s0 += __shfl_xor_sync(~0u, s0, 1); s0 += __shfl_xor_sync(~0u, s0, 2);
        s1 += __shfl_xor_sync(~0u, s1, 1); s1 += __shfl_xor_sync(~0u, s1, 2);
        SCB[2 * r0 + wn] = s0; SCB[2 * r1 + wn] = s1;
        __syncthreads();
        float i0 = 1.0f / (SCB[2 * r0] + SCB[2 * r0 + 1]);
        float i1 = 1.0f / (SCB[2 * r1] + SCB[2 * r1 + 1]);
#pragma unroll
        for (int i = 0; i < 8; i++) {
            acc[4*i] *= i0; acc[4*i+1] *= i0; acc[4*i+2] *= i1; acc[4*i+3] *= i1;
        }
        __syncthreads();        // all Q reads done before overwrite
        simg(B0, acc, r0, wn, g, q);   // P -> BUF0
        __syncthreads();
    }

    // ==== Phase 5: AO = P @ V -> BUF2 (K dead) ====
    zacc(acc);
    gfused(B0, B0 + 32768, B1, B1 + 32768, acc, m0, wn, noff, khalf);
    __syncthreads();            // K reads long done; P reads done before phase-6 staging
    simg(B2, acc, r0, wn, g, q);   // AO

    // ==== Phase 6: U = LN(AO @ Wo + bo + (x+te)) -> BUF0 ====
    __syncthreads();            // P reads done (stage overwrites BUF0lo)
    stage2(g_w[3], Wc, g_w[3] + 32768, smc + BUF0 + 32768, tid);
    __syncthreads();
    zacc(acc);
    gfused(B2, B2 + 32768, W, B0 + 32768, acc, m0, wn, noff, khalf);
    biasc(acc, bo, wn, q);
#pragma unroll
    for (int i = 0; i < 8; i++) {
        int c = 64 * wn + 8 * i + 2 * q;
        float2 xa = *(const float2*)(xb + (size_t)r0 * TSTRIDE + c);
        float2 ta = *(const float2*)(teb + (size_t)r0 * TSTRIDE + c);
        acc[4*i] += xa.x + ta.x; acc[4*i+1] += xa.y + ta.y;
        float2 xc = *(const float2*)(xb + (size_t)r1 * TSTRIDE + c);
        float2 tc = *(const float2*)(teb + (size_t)r1 * TSTRIDE + c);
        acc[4*i+2] += xc.x + tc.x; acc[4*i+3] += xc.y + tc.y;
    }
    {   // LayerNorm
        float s0 = 0, s1 = 0;
#pragma unroll
        for (int i = 0; i < 8; i++) { s0 += acc[4*i] + acc[4*i+1]; s1 += acc[4*i+2] + acc[4*i+3]; }
        s0 += __shfl_xor_sync(~0u, s0, 1); s0 += __shfl_xor_sync(~0u, s0, 2);
        s1 += __shfl_xor_sync(~0u, s1, 1); s1 += __shfl_xor_sync(~0u, s1, 2);
        SCA[2 * r0 + wn] = s0; SCA[2 * r1 + wn] = s1;
        __syncthreads();
        float mu0 = (SCA[2*r0] + SCA[2*r0+1]) * 0.0078125f;
        float mu1 = (SCA[2*r1] + SCA[2*r1+1]) * 0.0078125f;
        float q0 = 0, q1 = 0;
#pragma unroll
        for (int i = 0; i < 8; i++) {
            acc[4*i] -= mu0; acc[4*i+1] -= mu0; acc[4*i+2] -= mu1; acc[4*i+3] -= mu1;
            q0 += acc[4*i]*acc[4*i] + acc[4*i+1]*acc[4*i+1];
            q1 += acc[4*i+2]*acc[4*i+2] + acc[4*i+3]*acc[4*i+3];
        }
        q0 += __shfl_xor_sync(~0u, q0, 1); q0 += __shfl_xor_sync(~0u, q0, 2);
        q1 += __shfl_xor_sync(~0u, q1, 1); q1 += __shfl_xor_sync(~0u, q1, 2);
        SCB[2 * r0 + wn] = q0; SCB[2 * r1 + wn] = q1;
        __syncthreads();
        float i0 = rsqrtf((SCB[2*r0] + SCB[2*r0+1]) * 0.0078125f + 1e-5f);
        float i1 = rsqrtf((SCB[2*r1] + SCB[2*r1+1]) * 0.0078125f + 1e-5f);
#pragma unroll
        for (int i = 0; i < 8; i++) {
            acc[4*i] *= i0; acc[4*i+1] *= i0; acc[4*i+2] *= i1; acc[4*i+3] *= i1;
        }
    }
    __syncthreads();            // Wol reads done before simg overwrites BUF0lo
    simg(B0, acc, r0, wn, g, q);   // U

    // ==== Phase 7: H = relu(U @ W1 + b1) -> BUF2 ====
    __syncthreads();            // AO reads done (stage overwrites BUF2lo); U visible
    stage2(g_w[4], Wc, g_w[4] + 32768, smc + BUF2 + 32768, tid);
    __syncthreads();
    zacc(acc);
    gfused(B0, B0 + 32768, W, B2 + 32768, acc, m0, wn, noff, khalf);
    biasc(acc, b1, wn, q);
#pragma unroll
    for (int i = 0; i < 32; i++) acc[i] = fmaxf(acc[i], 0.0f);
    __syncthreads();            // W1l reads done before simg overwrites BUF2lo
    simg(B2, acc, r0, wn, g, q);   // H

    // ==== Phase 8: out = LN(H @ W2 + b2 + U) -> gmem (W2: hi in W, lo in BUF1) ====
    __syncthreads();            // V^T reads long done; H visible
    stage2(g_w[5], Wc, g_w[5] + 32768, smc + BUF1, tid);
    __syncthreads();
    zacc(acc);
    gfused(B2, B2 + 32768, W, B1, acc, m0, wn, noff, khalf);
    biasc(acc, b2, wn, q);
#pragma unroll
    for (int i = 0; i < 8; i++) {     // + U residual (hi+lo reconstruct from BUF0)
        uint32_t a0 = B0 + (uint32_t)(r0 * 256) + SWC(8 * wn + i, g) + 4 * q;
        uint32_t h, l;
        LDS32(h, a0); LDS32(l, a0 + 32768);
        float2 hf = bf2f2(h), lf = bf2f2(l);
        acc[4*i] += hf.x + lf.x; acc[4*i+1] += hf.y + lf.y;
        LDS32(h, a0 + 2048); LDS32(l, a0 + 2048 + 32768);
        hf = bf2f2(h); lf = bf2f2(l);
        acc[4*i+2] += hf.x + lf.x; acc[4*i+3] += hf.y + lf.y;
    }
    {   // final LayerNorm
        float s0 = 0, s1 = 0;
#pragma unroll
        for (int i = 0; i < 8; i++) { s0 += acc[4*i] + acc[4*i+1]; s1 += acc[4*i+2] + acc[4*i+3]; }
        s0 += __shfl_xor_sync(~0u, s0, 1); s0 += __shfl_xor_sync(~0u, s0, 2);
        s1 += __shfl_xor_sync(~0u, s1, 1); s1 += __shfl_xor_sync(~0u, s1, 2);
        SCA[2 * r0 + wn] = s0; SCA[2 * r1 + wn] = s1;
        __syncthreads();
        float mu0 = (SCA[2*r0] + SCA[2*r0+1]) * 0.0078125f;
        float mu1 = (SCA[2*r1] + SCA[2*r1+1]) * 0.0078125f;
        float q0 = 0, q1 = 0;
#pragma unroll
        for (int i = 0; i < 8; i++) {
            acc[4*i] -= mu0; acc[4*i+1] -= mu0; acc[4*i+2] -= mu1; acc[4*i+3] -= mu1;
            q0 += acc[4*i]*acc[4*i] + acc[4*i+1]*acc[4*i+1];
            q1 += acc[4*i+2]*acc[4*i+2] + acc[4*i+3]*acc[4*i+3];
        }
        q0 += __shfl_xor_sync(~0u, q0, 1); q0 += __shfl_xor_sync(~0u, q0, 2);
        q1 += __shfl_xor_sync(~0u, q1, 1); q1 += __shfl_xor_sync(~0u, q1, 2);
        SCB[2 * r0 + wn] = q0; SCB[2 * r1 + wn] = q1;
        __syncthreads();
        float i0 = rsqrtf((SCB[2*r0] + SCB[2*r0+1]) * 0.0078125f + 1e-5f);
        float i1 = rsqrtf((SCB[2*r1] + SCB[2*r1+1]) * 0.0078125f + 1e-5f);
#pragma unroll
        for (int i = 0; i < 8; i++) {
            int c = 64 * wn + 8 * i + 2 * q;
            *(float2*)(ob + (size_t)r0 * TSTRIDE + c) =
                make_float2(acc[4*i] * i0, acc[4*i+1] * i0);
            *(float2*)(ob + (size_t)r1 * TSTRIDE + c) =
                make_float2(acc[4*i+2] * i1, acc[4*i+3] * i1);
        }
    }
}

extern "C" void kernel_launch(void* const* d_in, const int* in_sizes, int n_in,
                              void* d_out, int out_size) {
    const float* x  = (const float*)d_in[0];
    const float* te = (const float*)d_in[1];
    const float* wq = (const float*)d_in[2];
    const float* bq = (const float*)d_in[3];
    const float* wk = (const float*)d_in[4];
    const float* bk = (const float*)d_in[5];
    const float* wv = (const float*)d_in[6];
    const float* bv = (const float*)d_in[7];
    const float* wo = (const float*)d_in[8];
    const float* bo = (const float*)d_in[9];
    const float* w1 = (const float*)d_in[10];
    const float* b1 = (const float*)d_in[11];
    const float* w2 = (const float*)d_in[12];
    const float* b2 = (const float*)d_in[13];
    float* out = (float*)d_out;

    prep_w<<<6, 256>>>(wk, wq, wv, wo, w1, w2);
    cudaFuncSetAttribute(fused_hmma3, cudaFuncAttributeMaxDynamicSharedMemorySize, SMEM_TOT);
    fused_hmma3<<<4096, THREADS, SMEM_TOT>>>(x, te, bq, bk, bv, bo, b1, b2, out);
}

// round 9
// speedup vs baseline: 3.5758x; 1.0968x over previous
#include <cuda_runtime.h>
#include <cuda_bf16.h>
#include <cstdint>

#define TSTRIDE 32768
#define THREADS 512

// smem byte offsets
#define BUF0 0u
#define BUF1 65536u
#define BUF2 131072u
#define WOFF 196608u
#define SCOFF 229376u     // SCA 256 floats | SCB 256 floats
#define SMEM_TOT 231424

// Weight images: [wk, wq, wv, wo, w1, w2], each = [hi 32KB | lo 32KB]
__device__ __align__(16) unsigned char g_w[6][65536];

#define SWC(c, r7) ((uint32_t)(((((c) ^ (r7)) & 7) | ((c) & 8)) << 4))

__device__ __forceinline__ uint32_t smem_u32(const void* p) {
    uint32_t a;
    asm("{ .reg .u64 t; cvta.to.shared.u64 t, %1; cvt.u32.u64 %0, t; }" : "=r"(a) : "l"(p));
    return a;
}
__device__ __forceinline__ uint32_t f2bf2(float a, float b) {   // lo=a, hi=b
    uint32_t r;
    asm("cvt.rn.bf16x2.f32 %0, %1, %2;" : "=r"(r) : "f"(b), "f"(a));
    return r;
}
__device__ __forceinline__ float2 bf2f2(uint32_t u) {
    __nv_bfloat162 h = *reinterpret_cast<__nv_bfloat162*>(&u);
    return __bfloat1622float2(h);
}
__device__ __forceinline__ void ldsm4(uint32_t* r, uint32_t a) {
    asm volatile("ldmatrix.sync.aligned.m8n8.x4.shared.b16 {%0,%1,%2,%3}, [%4];"
        : "=r"(r[0]), "=r"(r[1]), "=r"(r[2]), "=r"(r[3]) : "r"(a));
}
__device__ __forceinline__ void mma_bf16(float* d, const uint32_t* a, uint32_t b0, uint32_t b1) {
    asm volatile("mma.sync.aligned.m16n8k16.row.col.f32.bf16.bf16.f32 "
        "{%0,%1,%2,%3}, {%4,%5,%6,%7}, {%8,%9}, {%0,%1,%2,%3};"
        : "+f"(d[0]), "+f"(d[1]), "+f"(d[2]), "+f"(d[3])
        : "r"(a[0]), "r"(a[1]), "r"(a[2]), "r"(a[3]), "r"(b0), "r"(b1));
}
#define STS32(a, v)  asm volatile("st.shared.b32 [%0], %1;" :: "r"(a), "r"(v) : "memory")
#define STS128(a, v0, v1, v2, v3) \
    asm volatile("st.shared.v4.b32 [%0], {%1,%2,%3,%4};" \
        :: "r"(a), "r"(v0), "r"(v1), "r"(v2), "r"(v3) : "memory")
#define LDS32(v, a)  asm volatile("ld.shared.b32 %0, [%1];" : "=r"(v) : "r"(a))
#define CP16(d, s) \
    asm volatile("cp.async.cg.shared.global [%0], [%1], 16;" :: "r"(d), "l"(s) : "memory")
#define CP_COMMIT  asm volatile("cp.async.commit_group;" ::: "memory")
#define CP_WAITALL asm volatile("cp.async.wait_group 0;" ::: "memory")
#define QRED(v) do { v += __shfl_xor_sync(~0u, v, 1); v += __shfl_xor_sync(~0u, v, 2); } while (0)

// ============ prep kernel ============
__global__ void prep_w(const float* __restrict__ wk, const float* __restrict__ wq,
                       const float* __restrict__ wv, const float* __restrict__ wo,
                       const float* __restrict__ w1, const float* __restrict__ w2) {
    const float* ws[6] = {wk, wq, wv, wo, w1, w2};
    const float* src = ws[blockIdx.x];
    unsigned char* dst = g_w[blockIdx.x];
    for (int e = threadIdx.x; e < 16384; e += blockDim.x) {
        int f = e >> 7, k = e & 127;
        float val = src[k * 128 + f];            // W^T[f][k]
        __nv_bfloat16 h = __float2bfloat16(val);
        __nv_bfloat16 l = __float2bfloat16(val - __bfloat162float(h));
        uint32_t off = (uint32_t)f * 256 + SWC(k >> 3, f & 7) + (uint32_t)(k & 7) * 2;
        *(__nv_bfloat16*)(dst + off) = h;
        *(__nv_bfloat16*)(dst + 32768 + off) = l;
    }
}

// ============ cp.async staging ============
__device__ __forceinline__ void cpa32(uint32_t dst, const unsigned char* src, int tid) {
#pragma unroll
    for (int i = 0; i < 4; i++)
        CP16(dst + (uint32_t)(tid * 16 + i * 8192), src + tid * 16 + i * 8192);
}
__device__ __forceinline__ void cpa64(uint32_t dst, const unsigned char* src, int tid) {
#pragma unroll
    for (int i = 0; i < 8; i++)
        CP16(dst + (uint32_t)(tid * 16 + i * 8192), src + tid * 16 + i * 8192);
}

// ============ GEMM cores ============
// acc += Ah@Bh + Al@Bh + Ah@Bl, A fragments double-buffered across k-chunks
__device__ __forceinline__ void gfused(uint32_t ahb, uint32_t alb, uint32_t bhb,
                                       uint32_t blb, float* acc, int m0, int wn,
                                       int noff, int khalf) {
    const int rr = noff & 7;
    const uint32_t arow = (uint32_t)((m0 + noff) * 256);
    uint32_t ah[2][4], al[2][4];
    ldsm4(ah[0], ahb + arow + SWC(khalf, rr));
    ldsm4(al[0], alb + arow + SWC(khalf, rr));
#pragma unroll
    for (int j = 0; j < 8; j++) {
        const uint32_t csw = SWC(2 * j + khalf, rr);
        const int cur = j & 1, nxt = cur ^ 1;
        if (j < 7) {
            const uint32_t csw2 = SWC(2 * (j + 1) + khalf, rr);
            ldsm4(ah[nxt], ahb + arow + csw2);
            ldsm4(al[nxt], alb + arow + csw2);
        }
#pragma unroll
        for (int t = 0; t < 4; t++) {
            const uint32_t brow = (uint32_t)((64 * wn + 16 * t + noff) * 256);
            uint32_t bh[4], bl[4];
            ldsm4(bh, bhb + brow + csw);
            ldsm4(bl, blb + brow + csw);
            mma_bf16(acc + 8 * t,     ah[cur], bh[0], bh[2]);
            mma_bf16(acc + 8 * t + 4, ah[cur], bh[1], bh[3]);
            mma_bf16(acc + 8 * t,     al[cur], bh[0], bh[2]);
            mma_bf16(acc + 8 * t + 4, al[cur], bh[1], bh[3]);
            mma_bf16(acc + 8 * t,     ah[cur], bl[0], bl[2]);
            mma_bf16(acc + 8 * t + 4, ah[cur], bl[1], bl[3]);
        }
    }
}
// acc += (Ah + Al) @ B
__device__ __forceinline__ void gAB(uint32_t ahb, uint32_t alb, uint32_t bb,
                                    float* acc, int m0, int wn, int noff, int khalf) {
    const int rr = noff & 7;
    const uint32_t arow = (uint32_t)((m0 + noff) * 256);
    uint32_t ah[2][4], al[2][4];
    ldsm4(ah[0], ahb + arow + SWC(khalf, rr));
    ldsm4(al[0], alb + arow + SWC(khalf, rr));
#pragma unroll
    for (int j = 0; j < 8; j++) {
        const uint32_t csw = SWC(2 * j + khalf, rr);
        const int cur = j & 1, nxt = cur ^ 1;
        if (j < 7) {
            const uint32_t csw2 = SWC(2 * (j + 1) + khalf, rr);
            ldsm4(ah[nxt], ahb + arow + csw2);
            ldsm4(al[nxt], alb + arow + csw2);
        }
#pragma unroll
        for (int t = 0; t < 4; t++) {
            uint32_t b[4];
            ldsm4(b, bb + (uint32_t)((64 * wn + 16 * t + noff) * 256) + csw);
            mma_bf16(acc + 8 * t,     ah[cur], b[0], b[2]);
            mma_bf16(acc + 8 * t + 4, ah[cur], b[1], b[3]);
            mma_bf16(acc + 8 * t,     al[cur], b[0], b[2]);
            mma_bf16(acc + 8 * t + 4, al[cur], b[1], b[3]);
        }
    }
}
// acc += A @ B
__device__ __forceinline__ void gA(uint32_t ab, uint32_t bb, float* acc,
                                   int m0, int wn, int noff, int khalf) {
    const int rr = noff & 7;
    const uint32_t arow = (uint32_t)((m0 + noff) * 256);
    uint32_t ah[2][4];
    ldsm4(ah[0], ab + arow + SWC(khalf, rr));
#pragma unroll
    for (int j = 0; j < 8; j++) {
        const uint32_t csw = SWC(2 * j + khalf, rr);
        const int cur = j & 1, nxt = cur ^ 1;
        if (j < 7) ldsm4(ah[nxt], ab + arow + SWC(2 * (j + 1) + khalf, rr));
#pragma unroll
        for (int t = 0; t < 4; t++) {
            uint32_t b[4];
            ldsm4(b, bb + (uint32_t)((64 * wn + 16 * t + noff) * 256) + csw);
            mma_bf16(acc + 8 * t,     ah[cur], b[0], b[2]);
            mma_bf16(acc + 8 * t + 4, ah[cur], b[1], b[3]);
        }
    }
}

__device__ __forceinline__ void zacc(float* acc) {
#pragma unroll
    for (int i = 0; i < 32; i++) acc[i] = 0.0f;
}

__device__ __forceinline__ void simg(uint32_t ibase, const float* acc, int r0, int wn,
                                     int g, int q) {
#pragma unroll
    for (int i = 0; i < 8; i++) {
        uint32_t a0 = ibase + (uint32_t)(r0 * 256) + SWC(8 * wn + i, g) + 4 * q;
        float x0 = acc[4*i], x1 = acc[4*i+1], x2 = acc[4*i+2], x3 = acc[4*i+3];
        uint32_t h0 = f2bf2(x0, x1), h1 = f2bf2(x2, x3);
        float2 f0 = bf2f2(h0), f1 = bf2f2(h1);
        uint32_t l0 = f2bf2(x0 - f0.x, x1 - f0.y), l1 = f2bf2(x2 - f1.x, x3 - f1.y);
        STS32(a0, h0);        STS32(a0 + 32768, l0);
        STS32(a0 + 2048, h1); STS32(a0 + 2048 + 32768, l1);
    }
}

__device__ __forceinline__ void biasc(float* acc, const float* __restrict__ bias, int wn, int q) {
#pragma unroll
    for (int i = 0; i < 8; i++) {
        float2 bb = __ldg((const float2*)(bias + 64 * wn + 8 * i + 2 * q));
        acc[4*i] += bb.x; acc[4*i+1] += bb.y; acc[4*i+2] += bb.x; acc[4*i+3] += bb.y;
    }
}

// ============ main kernel ============
__global__ void __launch_bounds__(THREADS, 1)
fused_hmma4(const float* __restrict__ x, const float* __restrict__ te,
            const float* __restrict__ bq, const float* __restrict__ bk,
            const float* __restrict__ bv, const float* __restrict__ bo,
            const float* __restrict__ b1, const float* __restrict__ b2,
            float* __restrict__ out) {
    extern __shared__ char smc[];
    const uint32_t sb = smem_u32(smc);
    const uint32_t B0 = sb + BUF0, B1 = sb + BUF1, B2 = sb + BUF2, W = sb + WOFF;
    float* SCA = (float*)(smc + SCOFF);
    float* SCB = SCA + 256;

    const int tid = threadIdx.x, lane = tid & 31, w = tid >> 5;
    const int wm = w >> 1, wn = w & 1;
    const int m0 = 16 * wm;
    const int g = lane >> 2, q = lane & 3;
    const int noff = ((lane >> 3) & 1) * 8 + (lane & 7);
    const int khalf = lane >> 4;
    const int r0 = m0 + g, r1 = r0 + 8;

    const int bn = blockIdx.x, b = bn >> 8, n = bn & 255;
    const float* xb  = x  + (size_t)b * 128 * TSTRIDE + (size_t)n * 128;
    const float* teb = te + (size_t)b * 128 * TSTRIDE + (size_t)n * 128;
    float* ob = out + (size_t)b * 128 * TSTRIDE + (size_t)n * 128;

    // G0: prefetch Wk -> BUF2, Wv -> BUF1, Wq-hi -> W (all dead space)
    cpa64(B2, g_w[0], tid);
    cpa64(B1, g_w[2], tid);
    cpa32(W, g_w[1], tid);
    CP_COMMIT;

    // ---- build X = x+te hi/lo image -> BUF0 (overlaps G0) ----
    {
        int row = tid >> 2, quarter = tid & 3;
        const float4* xr = (const float4*)(xb  + (size_t)row * TSTRIDE + 32 * quarter);
        const float4* tr = (const float4*)(teb + (size_t)row * TSTRIDE + 32 * quarter);
#pragma unroll
        for (int ci = 0; ci < 4; ci++) {
            float4 a = xr[2*ci], c = tr[2*ci], a2 = xr[2*ci+1], c2 = tr[2*ci+1];
            float v0 = a.x + c.x, v1 = a.y + c.y, v2 = a.z + c.z, v3 = a.w + c.w;
            float v4 = a2.x + c2.x, v5 = a2.y + c2.y, v6 = a2.z + c2.z, v7 = a2.w + c2.w;
            uint32_t h0 = f2bf2(v0, v1), h1 = f2bf2(v2, v3);
            uint32_t h2 = f2bf2(v4, v5), h3 = f2bf2(v6, v7);
            float2 e0 = bf2f2(h0), e1 = bf2f2(h1), e2 = bf2f2(h2), e3 = bf2f2(h3);
            uint32_t l0 = f2bf2(v0 - e0.x, v1 - e0.y), l1 = f2bf2(v2 - e1.x, v3 - e1.y);
            uint32_t l2 = f2bf2(v4 - e2.x, v5 - e2.y), l3 = f2bf2(v6 - e3.x, v7 - e3.y);
            uint32_t addr = B0 + (uint32_t)row * 256 + SWC(4 * quarter + ci, row & 7);
            STS128(addr, h0, h1, h2, h3);
            STS128(addr + 32768, l0, l1, l2, l3);
        }
    }
    CP_WAITALL;
    __syncthreads();                                       // X + G0 visible

    float acc[32];

    // ==== Phase 1: K = X @ Wk -> BUF2 ====
    zacc(acc);
    gfused(B0, B0 + 32768, B2, B2 + 32768, acc, m0, wn, noff, khalf);
    biasc(acc, bk, wn, q);
    __syncthreads();                                       // Wk reads done
    simg(B2, acc, r0, wn, g, q);                           // K image

    // ==== Phase 2: V^T = Wv^T @ X -> BUF1 (A = Wv image in BUF1) ====
    zacc(acc);
    gfused(B1, B1 + 32768, B0, B0 + 32768, acc, m0, wn, noff, khalf);
    {
        float bv0 = __ldg(bv + r0), bv1 = __ldg(bv + r1);
#pragma unroll
        for (int i = 0; i < 8; i++) {
            acc[4*i] += bv0; acc[4*i+1] += bv0; acc[4*i+2] += bv1; acc[4*i+3] += bv1;
        }
    }
    __syncthreads();                                       // Wv reads done
    simg(B1, acc, r0, wn, g, q);                           // V^T image

    // ==== Phase 3: Q = X @ Wq -> BUF0 (2-stage through W) ====
    zacc(acc);
    gAB(B0, B0 + 32768, W, acc, m0, wn, noff, khalf);      // (Xh+Xl)@Wqh
    __syncthreads();                                       // Wq-hi reads done
    cpa32(W, g_w[1] + 32768, tid);
    CP_COMMIT; CP_WAITALL;
    __syncthreads();                                       // Wq-lo visible
    gA(B0, W, acc, m0, wn, noff, khalf);                   // Xh@Wql
    biasc(acc, bq, wn, q);
    __syncthreads();                                       // X + Wq-lo reads done
    cpa32(W, g_w[3], tid); CP_COMMIT;                      // G2: Wo-hi -> W (overlaps S)
    simg(B0, acc, r0, wn, g, q);                           // Q image
    __syncthreads();                                       // Q + V^T visible

    // ==== Phase 4: S = 0.25*Q@K^T, causal softmax (no max-sub) -> P -> BUF0 ====
    zacc(acc);
    gfused(B0, B0 + 32768, B2, B2 + 32768, acc, m0, wn, noff, khalf);
    {
        float s0 = 0, s1 = 0;
#pragma unroll
        for (int i = 0; i < 8; i++) {
            int c0 = 64 * wn + 8 * i + 2 * q;
            float p0 = (c0     <= r0) ? __expf(acc[4*i]   * 0.25f) : 0.0f;
            float p1 = (c0 + 1 <= r0) ? __expf(acc[4*i+1] * 0.25f) : 0.0f;
            float p2 = (c0     <= r1) ? __expf(acc[4*i+2] * 0.25f) : 0.0f;
            float p3 = (c0 + 1 <= r1) ? __expf(acc[4*i+3] * 0.25f) : 0.0f;
            acc[4*i] = p0; acc[4*i+1] = p1; acc[4*i+2] = p2; acc[4*i+3] = p3;
            s0 += p0 + p1; s1 += p2 + p3;
        }
        QRED(s0); QRED(s1);
        SCA[2 * r0 + wn] = s0; SCA[2 * r1 + wn] = s1;
        __syncthreads();                                   // sums ready; Q,K reads done
        float i0 = 1.0f / (SCA[2 * r0] + SCA[2 * r0 + 1]);
        float i1 = 1.0f / (SCA[2 * r1] + SCA[2 * r1 + 1]);
#pragma unroll
        for (int i = 0; i < 8; i++) {
            acc[4*i] *= i0; acc[4*i+1] *= i0; acc[4*i+2] *= i1; acc[4*i+3] *= i1;
        }
    }
    cpa32(B2 + 32768, g_w[3] + 32768, tid); CP_COMMIT;     // G3: Wo-lo -> B2lo (K dead)
    simg(B0, acc, r0, wn, g, q);                           // P image
    __syncthreads();                                       // P visible

    // ==== Phase 5: AO = P @ V -> BUF0 ====
    zacc(acc);
    gfused(B0, B0 + 32768, B1, B1 + 32768, acc, m0, wn, noff, khalf);
    __syncthreads();                                       // P + V^T reads done
    simg(B0, acc, r0, wn, g, q);                           // AO image (overwrites P)
    CP_WAITALL;
    __syncthreads();                                       // AO + Wo(hi,lo) visible
    cpa64(B1, g_w[4], tid); CP_COMMIT;                     // G4: W1 -> BUF1 (V^T dead), overlaps O

    // ==== Phase 6: U = LN(AO @ Wo + bo + (x+te)) -> BUF2 ====
    zacc(acc);
    gfused(B0, B0 + 32768, W, B2 + 32768, acc, m0, wn, noff, khalf);
    biasc(acc, bo, wn, q);
#pragma unroll
    for (int i = 0; i < 8; i++) {
        int c = 64 * wn + 8 * i + 2 * q;
        float2 xa = *(const float2*)(xb + (size_t)r0 * TSTRIDE + c);
        float2 ta = *(const float2*)(teb + (size_t)r0 * TSTRIDE + c);
        acc[4*i] += xa.x + ta.x; acc[4*i+1] += xa.y + ta.y;
        float2 xc = *(const float2*)(xb + (size_t)r1 * TSTRIDE + c);
        float2 tc = *(const float2*)(teb + (size_t)r1 * TSTRIDE + c);
        acc[4*i+2] += xc.x + tc.x; acc[4*i+3] += xc.y + tc.y;
    }
    {   // single-round LN: (sum, sumsq)
        float s0 = 0, s1 = 0, q0 = 0, q1 = 0;
#pragma unroll
        for (int i = 0; i < 8; i++) {
            s0 += acc[4*i] + acc[4*i+1]; s1 += acc[4*i+2] + acc[4*i+3];
            q0 += acc[4*i]*acc[4*i] + acc[4*i+1]*acc[4*i+1];
            q1 += acc[4*i+2]*acc[4*i+2] + acc[4*i+3]*acc[4*i+3];
        }
        QRED(s0); QRED(s1); QRED(q0); QRED(q1);
        SCA[2 * r0 + wn] = s0; SCA[2 * r1 + wn] = s1;
        SCB[2 * r0 + wn] = q0; SCB[2 * r1 + wn] = q1;
        __syncthreads();                                   // also Wo reads done
        float mu0 = (SCA[2*r0] + SCA[2*r0+1]) * 0.0078125f;
        float mu1 = (SCA[2*r1] + SCA[2*r1+1]) * 0.0078125f;
        float v0 = (SCB[2*r0] + SCB[2*r0+1]) * 0.0078125f - mu0 * mu0;
        float v1 = (SCB[2*r1] + SCB[2*r1+1]) * 0.0078125f - mu1 * mu1;
        float i0 = rsqrtf(v0 + 1e-5f), i1 = rsqrtf(v1 + 1e-5f);
#pragma unroll
        for (int i = 0; i < 8; i++) {
            acc[4*i] = (acc[4*i] - mu0) * i0;   acc[4*i+1] = (acc[4*i+1] - mu0) * i0;
            acc[4*i+2] = (acc[4*i+2] - mu1) * i1; acc[4*i+3] = (acc[4*i+3] - mu1) * i1;
        }
    }
    cpa32(W, g_w[5], tid); CP_COMMIT;                      // G5: W2-hi -> W (W dead), overlaps FFN1
    simg(B2, acc, r0, wn, g, q);                           // U image (overwrites Wo-lo)
    CP_WAITALL;
    __syncthreads();                                       // U + W1 visible

    // ==== Phase 7: H = relu(U @ W1 + b1) -> BUF0 ====
    zacc(acc);
    gfused(B2, B2 + 32768, B1, B1 + 32768, acc, m0, wn, noff, khalf);
    biasc(acc, b1, wn, q);
#pragma unroll
    for (int i = 0; i < 32; i++) acc[i] = fmaxf(acc[i], 0.0f);
    __syncthreads();                                       // W1 reads done
    cpa32(B1 + 32768, g_w[5] + 32768, tid); CP_COMMIT;     // G6: W2-lo -> BUF1lo
    simg(B0, acc, r0, wn, g, q);                           // H image
    CP_WAITALL;
    __syncthreads();                                       // H + W2 visible

    // ==== Phase 8: out = LN(H @ W2 + b2 + U) -> gmem ====
    zacc(acc);
    gfused(B0, B0 + 32768, W, B1 + 32768, acc, m0, wn, noff, khalf);
    biasc(acc, b2, wn, q);
#pragma unroll
    for (int i = 0; i < 8; i++) {     // + U residual (hi+lo from BUF2)
        uint32_t a0 = B2 + (uint32_t)(r0 * 256) + SWC(8 * wn + i, g) + 4 * q;
        uint32_t h, l;
        LDS32(h, a0); LDS32(l, a0 + 32768);
        float2 hf = bf2f2(h), lf = bf2f2(l);
        acc[4*i] += hf.x + lf.x; acc[4*i+1] += hf.y + lf.y;
        LDS32(h, a0 + 2048); LDS32(l, a0 + 2048 + 32768);
        hf = bf2f2(h); lf = bf2f2(l);
        acc[4*i+2] += hf.x + lf.x; acc[4*i+3] += hf.y + lf.y;
    }
    {   // single-round final LN
        float s0 = 0, s1 = 0, q0 = 0, q1 = 0;
#pragma unroll
        for (int i = 0; i < 8; i++) {
            s0 += acc[4*i] + acc[4*i+1]; s1 += acc[4*i+2] + acc[4*i+3];
            q0 += acc[4*i]*acc[4*i] + acc[4*i+1]*acc[4*i+1];
            q1 += acc[4*i+2]*acc[4*i+2] + acc[4*i+3]*acc[4*i+3];
        }
        QRED(s0); QRED(s1); QRED(q0); QRED(q1);
        SCA[2 * r0 + wn] = s0; SCA[2 * r1 + wn] = s1;
        SCB[2 * r0 + wn] = q0; SCB[2 * r1 + wn] = q1;
        __syncthreads();
        float mu0 = (SCA[2*r0] + SCA[2*r0+1]) * 0.0078125f;
        float mu1 = (SCA[2*r1] + SCA[2*r1+1]) * 0.0078125f;
        float v0 = (SCB[2*r0] + SCB[2*r0+1]) * 0.0078125f - mu0 * mu0;
        float v1 = (SCB[2*r1] + SCB[2*r1+1]) * 0.0078125f - mu1 * mu1;
        float i0 = rsqrtf(v0 + 1e-5f), i1 = rsqrtf(v1 + 1e-5f);
#pragma unroll
        for (int i = 0; i < 8; i++) {
            int c = 64 * wn + 8 * i + 2 * q;
            *(float2*)(ob + (size_t)r0 * TSTRIDE + c) =
                make_float2((acc[4*i] - mu0) * i0, (acc[4*i+1] - mu0) * i0);
            *(float2*)(ob + (size_t)r1 * TSTRIDE + c) =
                make_float2((acc[4*i+2] - mu1) * i1, (acc[4*i+3] - mu1) * i1);
        }
    }
}

extern "C" void kernel_launch(void* const* d_in, const int* in_sizes, int n_in,
                              void* d_out, int out_size) {
    const float* x  = (const float*)d_in[0];
    const float* te = (const float*)d_in[1];
    const float* wq = (const float*)d_in[2];
    const float* bq = (const float*)d_in[3];
    const float* wk = (const float*)d_in[4];
    const float* bk = (const float*)d_in[5];
    const float* wv = (const float*)d_in[6];
    const float* bv = (const float*)d_in[7];
    const float* wo = (const float*)d_in[8];
    const float* bo = (const float*)d_in[9];
    const float* w1 = (const float*)d_in[10];
    const float* b1 = (const float*)d_in[11];
    const float* w2 = (const float*)d_in[12];
    const float* b2 = (const float*)d_in[13];
    float* out = (float*)d_out;

    prep_w<<<6, 256>>>(wk, wq, wv, wo, w1, w2);
    cudaFuncSetAttribute(fused_hmma4, cudaFuncAttributeMaxDynamicSharedMemorySize, SMEM_TOT);
    fused_hmma4<<<4096, THREADS, SMEM_TOT>>>(x, te, bq, bk, bv, bo, b1, b2, out);
}